// round 10
// baseline (speedup 1.0000x reference)
#include <cuda_runtime.h>
#include <cuda_bf16.h>
#include <cuda_fp16.h>
#include <cstdint>

#define BATCH   512
#define FCIN    4096
#define EMBED   1024
#define NASPECT 2000
#define NASPAD  2048
#define NBRANDS 10000

// ---------------------------------------------------------------------------
// Scratch. A-side operands fp16; B-side is split in-GEMM from fp32 inputs.
// ---------------------------------------------------------------------------
__device__ __align__(256) __half g_imgF[BATCH * FCIN];
__device__ __align__(256) __half g_Hf[BATCH * FCIN];     // lrelu out, fp16
__device__ __align__(256) __half g_Gf[BATCH * NASPAD];   // gathered, fp16, K-padded
__device__ __align__(256) float g_F[BATCH * EMBED];
__device__ __align__(256) float g_V[BATCH * EMBED];

// ---------------------------------------------------------------------------
// PTX helpers
// ---------------------------------------------------------------------------
__device__ __forceinline__ uint32_t smem_u32(const void* p) {
    uint32_t a;
    asm("{ .reg .u64 t; cvta.to.shared.u64 t, %1; cvt.u32.u64 %0, t; }"
        : "=r"(a) : "l"(p));
    return a;
}
__device__ __forceinline__ void ldsm4(uint32_t* r, uint32_t addr) {
    asm volatile("ldmatrix.sync.aligned.m8n8.x4.shared.b16 {%0,%1,%2,%3}, [%4];"
        : "=r"(r[0]), "=r"(r[1]), "=r"(r[2]), "=r"(r[3]) : "r"(addr));
}
__device__ __forceinline__ void ldsm2t(uint32_t* r, uint32_t addr) {
    asm volatile("ldmatrix.sync.aligned.m8n8.x2.trans.shared.b16 {%0,%1}, [%2];"
        : "=r"(r[0]), "=r"(r[1]) : "r"(addr));
}
__device__ __forceinline__ void mma_f16(float* d, const uint32_t* a, const uint32_t* b) {
    asm volatile("mma.sync.aligned.m16n8k16.row.col.f32.f16.f16.f32 "
        "{%0,%1,%2,%3}, {%4,%5,%6,%7}, {%8,%9}, {%0,%1,%2,%3};"
        : "+f"(d[0]), "+f"(d[1]), "+f"(d[2]), "+f"(d[3])
        : "r"(a[0]), "r"(a[1]), "r"(a[2]), "r"(a[3]), "r"(b[0]), "r"(b[1]));
}
__device__ __forceinline__ void cpa16(uint32_t d, const void* s) {
    asm volatile("cp.async.cg.shared.global [%0], [%1], 16;" :: "r"(d), "l"(s));
}
#define CPA_COMMIT() asm volatile("cp.async.commit_group;" ::: "memory")
#define CPA_WAIT(n)  asm volatile("cp.async.wait_group %0;" :: "n"(n) : "memory")

__device__ __forceinline__ void split2h(float x, __half& h, __half& l) {
    h = __float2half_rn(x);
    l = __float2half_rn(x - __half2float(h));
}
__device__ __forceinline__ uint32_t pack_f16(__half a, __half b) {
    return (uint32_t)*(uint16_t*)&a | ((uint32_t)*(uint16_t*)&b << 16);
}
__device__ __forceinline__ void sts64(uint32_t addr, uint32_t x, uint32_t y) {
    asm volatile("st.shared.v2.u32 [%0], {%1, %2};" :: "r"(addr), "r"(x), "r"(y));
}

// ---------------------------------------------------------------------------
// fp16 2-MMA split GEMM with in-kernel B split:
//   C = A·fp16hi(B) + A·fp16lo(B)
// A: [M,K] fp16 (cp.async). B: [K,N] fp32 source, LDG'd per tile, split to
// hi/lo fp16 in registers, STS'd into double-buffered smem; ldmatrix.trans
// feeds fragments. Rows k >= Kvalid are zero (A is zero-padded there too).
// EPI: 0 = +bias, lrelu, write fp16; 1 = +bias fp32; 2 = fp32.
// ---------------------------------------------------------------------------
template<int BM, int BN, int BK, int WM, int WN, int EPI>
__global__ void __launch_bounds__(256)
gemm_f16_fuse(const __half* __restrict__ A, const float* __restrict__ Bsrc,
              const float* __restrict__ bias, int K, int Kvalid, int ldb, int ldc,
              float* __restrict__ Cf, __half* __restrict__ Ch)
{
    constexpr int SA = (BK + 8) * 2;
    constexpr int SB = (BN + 8) * 2;
    constexpr int OFF_A  = 0;
    constexpr int OFF_BH = BM * SA;
    constexpr int OFF_BL = BM * SA + BK * SB;
    constexpr int BUFB = BM * SA + 2 * BK * SB;
    constexpr int MI = WM / 16, NI = WN / 8;
    constexpr int KS = BK / 16;
    constexpr int AK8 = BK / 8;
    constexpr int BN4 = BN / 4;                 // float4s per B row
    constexpr int BJ  = BK * BN4 / 256;         // float4s per thread per chunk

    extern __shared__ __align__(128) char smem[];
    const uint32_t sb = smem_u32(smem);
    const int tid = threadIdx.x, wid = tid >> 5, lane = tid & 31;
    const int wm = wid % (BM / WM), wn = wid / (BM / WM);
    const int rowbase = blockIdx.y * BM, colbase = blockIdx.x * BN;

    const __half* srcA = A + (size_t)rowbase * K;
    const float*  srcB = Bsrc + colbase;

    float acc[MI][NI][4];
    #pragma unroll
    for (int i = 0; i < MI; i++)
        #pragma unroll
        for (int j = 0; j < NI; j++)
            #pragma unroll
            for (int q = 0; q < 4; q++) acc[i][j][q] = 0.f;

    const uint32_t aBase = (uint32_t)((wm * WM + (lane & 15)) * SA + (lane >> 4) * 16);
    const uint32_t bBase = (uint32_t)((lane & 15) * SB + (wn * WN) * 2);

    float4 breg[BJ];

    auto ldgB = [&](int chunk) {
        const int k0 = chunk * BK;
        #pragma unroll
        for (int j = 0; j < BJ; j++) {
            int idx = tid + j * 256;
            int r = idx / BN4, cc = idx % BN4;
            int row = k0 + r;
            if (row < Kvalid)
                breg[j] = ((const float4*)(srcB + (size_t)row * ldb))[cc];
            else
                breg[j] = make_float4(0.f, 0.f, 0.f, 0.f);
        }
    };
    auto stsB = [&](int p) {
        const uint32_t tb = sb + p * BUFB;
        #pragma unroll
        for (int j = 0; j < BJ; j++) {
            int idx = tid + j * 256;
            int r = idx / BN4, cc = idx % BN4;
            __half h0,l0,h1,l1,h2,l2,h3,l3;
            split2h(breg[j].x, h0, l0); split2h(breg[j].y, h1, l1);
            split2h(breg[j].z, h2, l2); split2h(breg[j].w, h3, l3);
            uint32_t d = (uint32_t)(r * SB + cc * 8);
            sts64(tb + OFF_BH + d, pack_f16(h0, h1), pack_f16(h2, h3));
            sts64(tb + OFF_BL + d, pack_f16(l0, l1), pack_f16(l2, l3));
        }
    };
    auto cpaA = [&](int chunk, int p) {
        const uint32_t tb = sb + p * BUFB;
        const int k0 = chunk * BK;
        #pragma unroll
        for (int i = tid; i < BM * AK8; i += 256) {
            int r = i / AK8, c = i % AK8;
            cpa16(tb + OFF_A + (uint32_t)(r * SA + c * 16),
                  srcA + (size_t)r * K + k0 + c * 8);
        }
        CPA_COMMIT();
    };

    const int NC = K / BK;
    ldgB(0);
    cpaA(0, 0);
    stsB(0);

    for (int c = 0; c < NC; c++) {
        const int p = c & 1;
        if (c + 1 < NC) {
            ldgB(c + 1);               // LDG issue; data lands during MMA(c)
            cpaA(c + 1, p ^ 1);
            CPA_WAIT(1);
        } else {
            CPA_WAIT(0);
        }
        __syncthreads();               // A(c) + BH/BL(c) ready for all warps

        const uint32_t tb = sb + p * BUFB;
        #pragma unroll
        for (int ks = 0; ks < KS; ks++) {
            uint32_t aF[MI][4], bH[NI][2], bL[NI][2];
            #pragma unroll
            for (int mi = 0; mi < MI; mi++)
                ldsm4(aF[mi], tb + OFF_A + aBase + (uint32_t)(mi * 16 * SA + ks * 32));
            #pragma unroll
            for (int ni = 0; ni < NI; ni++) {
                uint32_t o = bBase + (uint32_t)(ks * 16 * SB + ni * 16);
                ldsm2t(bH[ni], tb + OFF_BH + o);
                ldsm2t(bL[ni], tb + OFF_BL + o);
            }
            #pragma unroll
            for (int mi = 0; mi < MI; mi++)
                #pragma unroll
                for (int ni = 0; ni < NI; ni++) {
                    mma_f16(acc[mi][ni], aF[mi], bH[ni]);
                    mma_f16(acc[mi][ni], aF[mi], bL[ni]);
                }
        }
        if (c + 1 < NC) stsB(p ^ 1);   // split next chunk into other buffer
        __syncthreads();               // all reads of buf p done before refill
    }

    // Epilogue. Frag map: d0,d1 -> row lane>>2, cols (lane&3)*2,+1; d2,d3 -> +8 rows.
    const int r0 = rowbase + wm * WM + (lane >> 2);
    const int c0 = colbase + wn * WN + (lane & 3) * 2;
    #pragma unroll
    for (int mi = 0; mi < MI; mi++) {
        #pragma unroll
        for (int ni = 0; ni < NI; ni++) {
            const int cc = c0 + ni * 8;
            float b0 = 0.f, b1 = 0.f;
            if (EPI == 0 || EPI == 1) { b0 = __ldg(&bias[cc]); b1 = __ldg(&bias[cc + 1]); }
            #pragma unroll
            for (int h = 0; h < 2; h++) {
                const int rr = r0 + mi * 16 + h * 8;
                float v0 = acc[mi][ni][2 * h]     + b0;
                float v1 = acc[mi][ni][2 * h + 1] + b1;
                if (EPI == 0) {
                    v0 = v0 > 0.f ? v0 : 0.01f * v0;
                    v1 = v1 > 0.f ? v1 : 0.01f * v1;
                    *(uint32_t*)(Ch + (size_t)rr * ldc + cc) =
                        pack_f16(__float2half_rn(v0), __float2half_rn(v1));
                } else {
                    *(float2*)(Cf + (size_t)rr * ldc + cc) = make_float2(v0, v1);
                }
            }
        }
    }
}

// ---------------------------------------------------------------------------
// fp32 -> fp16 cast (image), 4 float4s per thread
// ---------------------------------------------------------------------------
__global__ void __launch_bounds__(256)
cast4_half(const float* __restrict__ in, __half* __restrict__ o, int n4)
{
    const int t = blockIdx.x * 256 + threadIdx.x;
    const int NT = gridDim.x * 256;
    #pragma unroll
    for (int k = 0; k < 4; k++) {
        int i = t + k * NT;
        if (i < n4) {
            float4 v = ((const float4*)in)[i];
            ((uint2*)o)[i] = make_uint2(
                pack_f16(__float2half_rn(v.x), __float2half_rn(v.y)),
                pack_f16(__float2half_rn(v.z), __float2half_rn(v.w)));
        }
    }
}

// Gather brand rows -> fp16 single, pad cols to NASPAD
__global__ void __launch_bounds__(256)
gather_cast(const float* __restrict__ emb, const int* __restrict__ idx,
            __half* __restrict__ o)
{
    const int b = blockIdx.x;
    int row = idx[b];
    row = row < 0 ? 0 : (row >= NBRANDS ? NBRANDS - 1 : row);
    const float4* src = (const float4*)(emb + (size_t)row * NASPECT);
    for (int j = threadIdx.x; j < NASPAD / 4; j += 256) {
        uint2 p = make_uint2(0, 0);
        if (j < NASPECT / 4) {
            float4 v = src[j];
            p = make_uint2(pack_f16(__float2half_rn(v.x), __float2half_rn(v.y)),
                           pack_f16(__float2half_rn(v.z), __float2half_rn(v.w)));
        }
        ((uint2*)(o + (size_t)b * NASPAD))[j] = p;
    }
}

// out[b] = dot(g_F[b,:], g_V[b,:]) / NASPECT
__global__ void __launch_bounds__(256)
final_dot(float* __restrict__ out)
{
    const int b = blockIdx.x;
    const float* f = g_F + (size_t)b * EMBED;
    const float* v = g_V + (size_t)b * EMBED;
    float s = 0.f;
    for (int i = threadIdx.x; i < EMBED; i += 256)
        s = fmaf(f[i], v[i], s);
    #pragma unroll
    for (int off = 16; off > 0; off >>= 1)
        s += __shfl_xor_sync(0xFFFFFFFFu, s, off);
    __shared__ float red[8];
    if ((threadIdx.x & 31) == 0) red[threadIdx.x >> 5] = s;
    __syncthreads();
    if (threadIdx.x < 8) {
        s = red[threadIdx.x];
        #pragma unroll
        for (int off = 4; off > 0; off >>= 1)
            s += __shfl_xor_sync(0xFFu, s, off);
        if (threadIdx.x == 0) out[b] = s * (1.0f / (float)NASPECT);
    }
}

// ---------------------------------------------------------------------------
#define SM_G1 (2 * (128 * (64 + 8) * 2 + 2 * 64 * (128 + 8) * 2))   // 106496
#define SM_G2 (2 * (64 * (64 + 8) * 2 + 2 * 64 * (64 + 8) * 2))     // 55296
#define G4(n4) (((n4) + 4 * 256 - 1) / (4 * 256))

extern "C" void kernel_launch(void* const* d_in, const int* in_sizes, int n_in,
                              void* d_out, int out_size)
{
    const float* image     = (const float*)d_in[0];
    const int*   brand     = (const int*)d_in[1];
    const float* W1        = (const float*)d_in[2];
    const float* b1        = (const float*)d_in[3];
    const float* W2        = (const float*)d_in[4];
    const float* b2        = (const float*)d_in[5];
    const float* brand_emb = (const float*)d_in[6];
    const float* aspects   = (const float*)d_in[7];
    float*       out       = (float*)d_out;

    static bool init = false;
    static __half *pImgF, *pHf, *pGf;
    static float *pF, *pV;
    if (!init) {
        cudaGetSymbolAddress((void**)&pImgF, g_imgF);
        cudaGetSymbolAddress((void**)&pHf,   g_Hf);
        cudaGetSymbolAddress((void**)&pGf,   g_Gf);
        cudaGetSymbolAddress((void**)&pF,    g_F);
        cudaGetSymbolAddress((void**)&pV,    g_V);
        cudaFuncSetAttribute((const void*)gemm_f16_fuse<128,128,64,64,32,0>,
                             cudaFuncAttributeMaxDynamicSharedMemorySize, SM_G1);
        cudaFuncSetAttribute((const void*)gemm_f16_fuse<64,64,64,32,16,2>,
                             cudaFuncAttributeMaxDynamicSharedMemorySize, SM_G2);
        cudaFuncSetAttribute((const void*)gemm_f16_fuse<64,64,64,32,16,1>,
                             cudaFuncAttributeMaxDynamicSharedMemorySize, SM_G2);
        init = true;
    }

    // A-side conversions only (B-side splits are fused into the GEMMs)
    cast4_half<<<G4(BATCH * FCIN / 4), 256>>>(image, pImgF, BATCH * FCIN / 4);
    gather_cast<<<BATCH, 256>>>(brand_emb, brand, pGf);

    // GEMM1: H = lrelu(image @ W1 + b1) -> fp16 ; B = W1 fp32 [K=4096, N=4096]
    gemm_f16_fuse<128,128,64,64,32,0><<<dim3(FCIN / 128, BATCH / 128), 256, SM_G1>>>(
        pImgF, W1, b1, FCIN, FCIN, FCIN, FCIN, nullptr, pHf);

    // GEMM3: V = gather @ aspects -> fp32 ; B = aspects fp32 [K=2000(pad 2048), N=1024]
    gemm_f16_fuse<64,64,64,32,16,2><<<dim3(EMBED / 64, BATCH / 64), 256, SM_G2>>>(
        pGf, aspects, nullptr, NASPAD, NASPECT, EMBED, EMBED, pV, nullptr);

    // GEMM2: F = H @ W2 + b2 -> fp32 ; B = W2 fp32 [K=4096, N=1024]
    gemm_f16_fuse<64,64,64,32,16,1><<<dim3(EMBED / 64, BATCH / 64), 256, SM_G2>>>(
        pHf, W2, b2, FCIN, FCIN, EMBED, EMBED, pF, nullptr);

    final_dot<<<BATCH, 256>>>(out);
}

// round 12
// speedup vs baseline: 1.4932x; 1.4932x over previous
#include <cuda_runtime.h>
#include <cuda_bf16.h>
#include <cuda_fp16.h>
#include <cstdint>

#define BATCH   512
#define FCIN    4096
#define EMBED   1024
#define NASPECT 2000
#define NASPAD  2048
#define NBRANDS 10000

// ---------------------------------------------------------------------------
// Scratch. GEMM1: A, B single fp16. GEMM2/3: A single fp16, B fp16 hi/lo.
// ---------------------------------------------------------------------------
__device__ __align__(256) __half g_imgF[BATCH * FCIN];
__device__ __align__(256) __half g_W1F[FCIN * FCIN];     // [K,N] single fp16
__device__ __align__(256) __half g_Hf[BATCH * FCIN];     // lrelu out, fp16
__device__ __align__(256) __half g_W2H[FCIN * EMBED];    // [K,N] hi
__device__ __align__(256) __half g_W2L[FCIN * EMBED];    // lo
__device__ __align__(256) __half g_Gf[BATCH * NASPAD];   // gathered, fp16, padded
__device__ __align__(256) __half g_ASH[NASPAD * EMBED];  // [Kpad,N] hi
__device__ __align__(256) __half g_ASL[NASPAD * EMBED];  // lo
__device__ __align__(256) float g_F[BATCH * EMBED];
__device__ __align__(256) float g_V[BATCH * EMBED];

// ---------------------------------------------------------------------------
// PTX helpers
// ---------------------------------------------------------------------------
__device__ __forceinline__ uint32_t smem_u32(const void* p) {
    uint32_t a;
    asm("{ .reg .u64 t; cvta.to.shared.u64 t, %1; cvt.u32.u64 %0, t; }"
        : "=r"(a) : "l"(p));
    return a;
}
__device__ __forceinline__ void ldsm4(uint32_t* r, uint32_t addr) {
    asm volatile("ldmatrix.sync.aligned.m8n8.x4.shared.b16 {%0,%1,%2,%3}, [%4];"
        : "=r"(r[0]), "=r"(r[1]), "=r"(r[2]), "=r"(r[3]) : "r"(addr));
}
__device__ __forceinline__ void ldsm2t(uint32_t* r, uint32_t addr) {
    asm volatile("ldmatrix.sync.aligned.m8n8.x2.trans.shared.b16 {%0,%1}, [%2];"
        : "=r"(r[0]), "=r"(r[1]) : "r"(addr));
}
__device__ __forceinline__ void mma_f16(float* d, const uint32_t* a, const uint32_t* b) {
    asm volatile("mma.sync.aligned.m16n8k16.row.col.f32.f16.f16.f32 "
        "{%0,%1,%2,%3}, {%4,%5,%6,%7}, {%8,%9}, {%0,%1,%2,%3};"
        : "+f"(d[0]), "+f"(d[1]), "+f"(d[2]), "+f"(d[3])
        : "r"(a[0]), "r"(a[1]), "r"(a[2]), "r"(a[3]), "r"(b[0]), "r"(b[1]));
}
__device__ __forceinline__ void cpa16(uint32_t d, const void* s) {
    asm volatile("cp.async.cg.shared.global [%0], [%1], 16;" :: "r"(d), "l"(s));
}
#define CPA_COMMIT() asm volatile("cp.async.commit_group;" ::: "memory")
#define CPA_WAIT(n)  asm volatile("cp.async.wait_group %0;" :: "n"(n) : "memory")

__device__ __forceinline__ void split2h(float x, __half& h, __half& l) {
    h = __float2half_rn(x);
    l = __float2half_rn(x - __half2float(h));
}
__device__ __forceinline__ uint32_t pack_f16(__half a, __half b) {
    return (uint32_t)*(uint16_t*)&a | ((uint32_t)*(uint16_t*)&b << 16);
}

// ---------------------------------------------------------------------------
// GEMM1 core: single fp16, 1 MMA per tile:  C = A·B
// A: [M,K] fp16. B: [K,N] fp16 (ldmatrix.trans). Epilogue: +bias, lrelu -> fp16.
// ---------------------------------------------------------------------------
template<int BM, int BN, int BK, int WM, int WN>
__global__ void __launch_bounds__(256)
gemm_f16x1(const __half* __restrict__ A, const __half* __restrict__ B,
           const float* __restrict__ bias, int K, int ldb, int ldc,
           __half* __restrict__ Ch)
{
    constexpr int SA = (BK + 8) * 2;
    constexpr int SB = (BN + 8) * 2;
    constexpr int OFF_A = 0;
    constexpr int OFF_B = BM * SA;
    constexpr int BUFB = BM * SA + BK * SB;
    constexpr int MI = WM / 16, NI = WN / 8;
    constexpr int KS = BK / 16;
    constexpr int AK8 = BK / 8;
    constexpr int BN8 = BN / 8;

    extern __shared__ __align__(128) char smem[];
    const uint32_t sb = smem_u32(smem);
    const int tid = threadIdx.x, wid = tid >> 5, lane = tid & 31;
    const int wm = wid % (BM / WM), wn = wid / (BM / WM);
    const int rowbase = blockIdx.y * BM, colbase = blockIdx.x * BN;

    const __half* srcA = A + (size_t)rowbase * K;
    const __half* srcB = B + colbase;

    float acc[MI][NI][4];
    #pragma unroll
    for (int i = 0; i < MI; i++)
        #pragma unroll
        for (int j = 0; j < NI; j++)
            #pragma unroll
            for (int q = 0; q < 4; q++) acc[i][j][q] = 0.f;

    const uint32_t aBase = (uint32_t)((wm * WM + (lane & 15)) * SA + (lane >> 4) * 16);
    const uint32_t bBase = (uint32_t)((lane & 15) * SB + (wn * WN) * 2);

    auto prefetch = [&](int chunk, int p) {
        const uint32_t tb = sb + p * BUFB;
        const int k0 = chunk * BK;
        #pragma unroll
        for (int i = tid; i < BM * AK8; i += 256) {
            int r = i / AK8, c = i % AK8;
            cpa16(tb + OFF_A + (uint32_t)(r * SA + c * 16),
                  srcA + (size_t)r * K + k0 + c * 8);
        }
        #pragma unroll
        for (int i = tid; i < BK * BN8; i += 256) {
            int r = i / BN8, c = i % BN8;
            cpa16(tb + OFF_B + (uint32_t)(r * SB + c * 16),
                  srcB + (size_t)(k0 + r) * ldb + c * 8);
        }
        CPA_COMMIT();
    };

    const int NC = K / BK;
    prefetch(0, 0);

    for (int c = 0; c < NC; c++) {
        const int p = c & 1;
        if (c + 1 < NC) { prefetch(c + 1, (c + 1) & 1); CPA_WAIT(1); }
        else            { CPA_WAIT(0); }
        __syncthreads();

        const uint32_t tb = sb + p * BUFB;
        #pragma unroll
        for (int ks = 0; ks < KS; ks++) {
            uint32_t aF[MI][4], bF[NI][2];
            #pragma unroll
            for (int mi = 0; mi < MI; mi++)
                ldsm4(aF[mi], tb + OFF_A + aBase + (uint32_t)(mi * 16 * SA + ks * 32));
            #pragma unroll
            for (int ni = 0; ni < NI; ni++)
                ldsm2t(bF[ni], tb + OFF_B + bBase + (uint32_t)(ks * 16 * SB + ni * 16));
            #pragma unroll
            for (int mi = 0; mi < MI; mi++)
                #pragma unroll
                for (int ni = 0; ni < NI; ni++)
                    mma_f16(acc[mi][ni], aF[mi], bF[ni]);
        }
        __syncthreads();
    }

    const int r0 = rowbase + wm * WM + (lane >> 2);
    const int c0 = colbase + wn * WN + (lane & 3) * 2;
    #pragma unroll
    for (int mi = 0; mi < MI; mi++) {
        #pragma unroll
        for (int ni = 0; ni < NI; ni++) {
            const int cc = c0 + ni * 8;
            const float b0 = __ldg(&bias[cc]), b1 = __ldg(&bias[cc + 1]);
            #pragma unroll
            for (int h = 0; h < 2; h++) {
                const int rr = r0 + mi * 16 + h * 8;
                float v0 = acc[mi][ni][2 * h]     + b0;
                float v1 = acc[mi][ni][2 * h + 1] + b1;
                v0 = v0 > 0.f ? v0 : 0.01f * v0;
                v1 = v1 > 0.f ? v1 : 0.01f * v1;
                *(uint32_t*)(Ch + (size_t)rr * ldc + cc) =
                    pack_f16(__float2half_rn(v0), __float2half_rn(v1));
            }
        }
    }
}

// ---------------------------------------------------------------------------
// fp16 2-MMA split GEMM (validated core):  C = A·Bh + A·Bl
// EPI: 1 = +bias fp32; 2 = fp32.
// ---------------------------------------------------------------------------
template<int BM, int BN, int BK, int WM, int WN, int EPI>
__global__ void __launch_bounds__(256)
gemm_f16x2(const __half* __restrict__ A,
           const __half* __restrict__ Bh, const __half* __restrict__ Bl,
           const float* __restrict__ bias, int K, int ldb, int ldc,
           float* __restrict__ Cf)
{
    constexpr int SA = (BK + 8) * 2;
    constexpr int SB = (BN + 8) * 2;
    constexpr int OFF_A  = 0;
    constexpr int OFF_BH = BM * SA;
    constexpr int OFF_BL = BM * SA + BK * SB;
    constexpr int BUFB = BM * SA + 2 * BK * SB;
    constexpr int MI = WM / 16, NI = WN / 8;
    constexpr int KS = BK / 16;
    constexpr int AK8 = BK / 8;
    constexpr int BN8 = BN / 8;

    extern __shared__ __align__(128) char smem[];
    const uint32_t sb = smem_u32(smem);
    const int tid = threadIdx.x, wid = tid >> 5, lane = tid & 31;
    const int wm = wid % (BM / WM), wn = wid / (BM / WM);
    const int rowbase = blockIdx.y * BM, colbase = blockIdx.x * BN;

    const __half* srcA = A + (size_t)rowbase * K;
    const __half* srcB[2] = { Bh + colbase, Bl + colbase };

    float acc[MI][NI][4];
    #pragma unroll
    for (int i = 0; i < MI; i++)
        #pragma unroll
        for (int j = 0; j < NI; j++)
            #pragma unroll
            for (int q = 0; q < 4; q++) acc[i][j][q] = 0.f;

    const uint32_t aBase = (uint32_t)((wm * WM + (lane & 15)) * SA + (lane >> 4) * 16);
    const uint32_t bBase = (uint32_t)((lane & 15) * SB + (wn * WN) * 2);

    auto prefetch = [&](int chunk, int p) {
        const uint32_t tb = sb + p * BUFB;
        const int k0 = chunk * BK;
        #pragma unroll
        for (int i = tid; i < BM * AK8; i += 256) {
            int r = i / AK8, c = i % AK8;
            cpa16(tb + OFF_A + (uint32_t)(r * SA + c * 16),
                  srcA + (size_t)r * K + k0 + c * 8);
        }
        #pragma unroll
        for (int i = tid; i < BK * BN8; i += 256) {
            int r = i / BN8, c = i % BN8;
            uint32_t d = (uint32_t)(r * SB + c * 16);
            cpa16(tb + OFF_BH + d, srcB[0] + (size_t)(k0 + r) * ldb + c * 8);
            cpa16(tb + OFF_BL + d, srcB[1] + (size_t)(k0 + r) * ldb + c * 8);
        }
        CPA_COMMIT();
    };

    const int NC = K / BK;
    prefetch(0, 0);

    for (int c = 0; c < NC; c++) {
        const int p = c & 1;
        if (c + 1 < NC) { prefetch(c + 1, (c + 1) & 1); CPA_WAIT(1); }
        else            { CPA_WAIT(0); }
        __syncthreads();

        const uint32_t tb = sb + p * BUFB;
        #pragma unroll
        for (int ks = 0; ks < KS; ks++) {
            uint32_t aF[MI][4], bH[NI][2], bL[NI][2];
            #pragma unroll
            for (int mi = 0; mi < MI; mi++)
                ldsm4(aF[mi], tb + OFF_A + aBase + (uint32_t)(mi * 16 * SA + ks * 32));
            #pragma unroll
            for (int ni = 0; ni < NI; ni++) {
                uint32_t o = bBase + (uint32_t)(ks * 16 * SB + ni * 16);
                ldsm2t(bH[ni], tb + OFF_BH + o);
                ldsm2t(bL[ni], tb + OFF_BL + o);
            }
            #pragma unroll
            for (int mi = 0; mi < MI; mi++)
                #pragma unroll
                for (int ni = 0; ni < NI; ni++) {
                    mma_f16(acc[mi][ni], aF[mi], bH[ni]);
                    mma_f16(acc[mi][ni], aF[mi], bL[ni]);
                }
        }
        __syncthreads();
    }

    const int r0 = rowbase + wm * WM + (lane >> 2);
    const int c0 = colbase + wn * WN + (lane & 3) * 2;
    #pragma unroll
    for (int mi = 0; mi < MI; mi++) {
        #pragma unroll
        for (int ni = 0; ni < NI; ni++) {
            const int cc = c0 + ni * 8;
            float b0 = 0.f, b1 = 0.f;
            if (EPI == 1) { b0 = __ldg(&bias[cc]); b1 = __ldg(&bias[cc + 1]); }
            #pragma unroll
            for (int h = 0; h < 2; h++) {
                const int rr = r0 + mi * 16 + h * 8;
                *(float2*)(Cf + (size_t)rr * ldc + cc) =
                    make_float2(acc[mi][ni][2 * h] + b0, acc[mi][ni][2 * h + 1] + b1);
            }
        }
    }
}

// ---------------------------------------------------------------------------
// Conversion kernels
// ---------------------------------------------------------------------------
// fp32 -> fp16 cast, 8 elems/thread (2x LDG.128 -> 1x STG.128), grid-stride x2.
__global__ void __launch_bounds__(256)
cast8_half(const float* __restrict__ in, __half* __restrict__ o, int n8)
{
    const int t = blockIdx.x * 256 + threadIdx.x;
    const int NT = gridDim.x * 256;
    #pragma unroll
    for (int k = 0; k < 2; k++) {
        int i = t + k * NT;
        if (i < n8) {
            float4 a = ((const float4*)in)[2 * i];
            float4 b = ((const float4*)in)[2 * i + 1];
            ((uint4*)o)[i] = make_uint4(
                pack_f16(__float2half_rn(a.x), __float2half_rn(a.y)),
                pack_f16(__float2half_rn(a.z), __float2half_rn(a.w)),
                pack_f16(__float2half_rn(b.x), __float2half_rn(b.y)),
                pack_f16(__float2half_rn(b.z), __float2half_rn(b.w)));
        }
    }
}

// fp32 -> fp16 hi/lo split with zero suffix (valid4..total4 -> 0)
__global__ void __launch_bounds__(256)
split4_half(const float* __restrict__ in, __half* __restrict__ hi,
            __half* __restrict__ lo, int total4, int valid4)
{
    const int t = blockIdx.x * 256 + threadIdx.x;
    const int NT = gridDim.x * 256;
    #pragma unroll
    for (int k = 0; k < 4; k++) {
        int i = t + k * NT;
        if (i < total4) {
            uint2 ph = make_uint2(0, 0), pl = make_uint2(0, 0);
            if (i < valid4) {
                float4 v = ((const float4*)in)[i];
                __half h[4], l[4];
                split2h(v.x, h[0], l[0]); split2h(v.y, h[1], l[1]);
                split2h(v.z, h[2], l[2]); split2h(v.w, h[3], l[3]);
                ph = make_uint2(pack_f16(h[0], h[1]), pack_f16(h[2], h[3]));
                pl = make_uint2(pack_f16(l[0], l[1]), pack_f16(l[2], l[3]));
            }
            ((uint2*)hi)[i] = ph;
            ((uint2*)lo)[i] = pl;
        }
    }
}

// Gather brand rows -> fp16 single, pad cols to NASPAD
__global__ void __launch_bounds__(256)
gather_cast(const float* __restrict__ emb, const int* __restrict__ idx,
            __half* __restrict__ o)
{
    const int b = blockIdx.x;
    int row = idx[b];
    row = row < 0 ? 0 : (row >= NBRANDS ? NBRANDS - 1 : row);
    const float4* src = (const float4*)(emb + (size_t)row * NASPECT);
    for (int j = threadIdx.x; j < NASPAD / 4; j += 256) {
        uint2 p = make_uint2(0, 0);
        if (j < NASPECT / 4) {
            float4 v = src[j];
            p = make_uint2(pack_f16(__float2half_rn(v.x), __float2half_rn(v.y)),
                           pack_f16(__float2half_rn(v.z), __float2half_rn(v.w)));
        }
        ((uint2*)(o + (size_t)b * NASPAD))[j] = p;
    }
}

// out[b] = dot(g_F[b,:], g_V[b,:]) / NASPECT
__global__ void __launch_bounds__(256)
final_dot(float* __restrict__ out)
{
    const int b = blockIdx.x;
    const float* f = g_F + (size_t)b * EMBED;
    const float* v = g_V + (size_t)b * EMBED;
    float s = 0.f;
    for (int i = threadIdx.x; i < EMBED; i += 256)
        s = fmaf(f[i], v[i], s);
    #pragma unroll
    for (int off = 16; off > 0; off >>= 1)
        s += __shfl_xor_sync(0xFFFFFFFFu, s, off);
    __shared__ float red[8];
    if ((threadIdx.x & 31) == 0) red[threadIdx.x >> 5] = s;
    __syncthreads();
    if (threadIdx.x < 8) {
        s = red[threadIdx.x];
        #pragma unroll
        for (int off = 4; off > 0; off >>= 1)
            s += __shfl_xor_sync(0xFFu, s, off);
        if (threadIdx.x == 0) out[b] = s * (1.0f / (float)NASPECT);
    }
}

// ---------------------------------------------------------------------------
#define SM_G1 (2 * (128 * (64 + 8) * 2 + 64 * (128 + 8) * 2))       // 71680
#define SM_G2 (2 * (64 * (64 + 8) * 2 + 2 * 64 * (64 + 8) * 2))     // 55296
#define G4(n4) (((n4) + 4 * 256 - 1) / (4 * 256))
#define G8(n8) (((n8) + 2 * 256 - 1) / (2 * 256))

extern "C" void kernel_launch(void* const* d_in, const int* in_sizes, int n_in,
                              void* d_out, int out_size)
{
    const float* image     = (const float*)d_in[0];
    const int*   brand     = (const int*)d_in[1];
    const float* W1        = (const float*)d_in[2];
    const float* b1        = (const float*)d_in[3];
    const float* W2        = (const float*)d_in[4];
    const float* b2        = (const float*)d_in[5];
    const float* brand_emb = (const float*)d_in[6];
    const float* aspects   = (const float*)d_in[7];
    float*       out       = (float*)d_out;

    static bool init = false;
    static __half *pImgF, *pW1F, *pHf, *pW2H, *pW2L, *pGf, *pASH, *pASL;
    static float *pF, *pV;
    if (!init) {
        cudaGetSymbolAddress((void**)&pImgF, g_imgF);
        cudaGetSymbolAddress((void**)&pW1F,  g_W1F);
        cudaGetSymbolAddress((void**)&pHf,   g_Hf);
        cudaGetSymbolAddress((void**)&pW2H,  g_W2H);
        cudaGetSymbolAddress((void**)&pW2L,  g_W2L);
        cudaGetSymbolAddress((void**)&pGf,   g_Gf);
        cudaGetSymbolAddress((void**)&pASH,  g_ASH);
        cudaGetSymbolAddress((void**)&pASL,  g_ASL);
        cudaGetSymbolAddress((void**)&pF,    g_F);
        cudaGetSymbolAddress((void**)&pV,    g_V);
        cudaFuncSetAttribute((const void*)gemm_f16x1<128,128,64,64,32>,
                             cudaFuncAttributeMaxDynamicSharedMemorySize, SM_G1);
        cudaFuncSetAttribute((const void*)gemm_f16x2<64,64,64,32,16,2>,
                             cudaFuncAttributeMaxDynamicSharedMemorySize, SM_G2);
        cudaFuncSetAttribute((const void*)gemm_f16x2<64,64,64,32,16,1>,
                             cudaFuncAttributeMaxDynamicSharedMemorySize, SM_G2);
        init = true;
    }

    // Operand conversions
    cast8_half<<<G8(BATCH * FCIN / 8), 256>>>(image, pImgF, BATCH * FCIN / 8);
    cast8_half<<<G8(FCIN * FCIN / 8), 256>>>(W1, pW1F, FCIN * FCIN / 8);
    split4_half<<<G4(FCIN * EMBED / 4), 256>>>(
        W2, pW2H, pW2L, FCIN * EMBED / 4, FCIN * EMBED / 4);
    split4_half<<<G4(NASPAD * EMBED / 4), 256>>>(
        aspects, pASH, pASL, NASPAD * EMBED / 4, NASPECT * EMBED / 4);
    gather_cast<<<BATCH, 256>>>(brand_emb, brand, pGf);

    // GEMM1 (1-term fp16): H = lrelu(image @ W1 + b1) -> fp16
    gemm_f16x1<128,128,64,64,32><<<dim3(FCIN / 128, BATCH / 128), 256, SM_G1>>>(
        pImgF, pW1F, b1, FCIN, FCIN, FCIN, pHf);

    // GEMM3 (2-term): V = gather(brand_emb) @ aspects -> fp32
    gemm_f16x2<64,64,64,32,16,2><<<dim3(EMBED / 64, BATCH / 64), 256, SM_G2>>>(
        pGf, pASH, pASL, nullptr, NASPAD, EMBED, EMBED, pV);

    // GEMM2 (2-term): F = H @ W2 + b2 -> fp32
    gemm_f16x2<64,64,64,32,16,1><<<dim3(EMBED / 64, BATCH / 64), 256, SM_G2>>>(
        pHf, pW2H, pW2L, b2, FCIN, EMBED, EMBED, pF);

    final_dot<<<BATCH, 256>>>(out);
}

// round 13
// speedup vs baseline: 1.7000x; 1.1385x over previous
#include <cuda_runtime.h>
#include <cuda_bf16.h>
#include <cuda_fp16.h>
#include <cstdint>

#define BATCH   512
#define FCIN    4096
#define EMBED   1024
#define NASPECT 2000
#define NASPAD  2048
#define NBRANDS 10000

// ---------------------------------------------------------------------------
// Scratch. All GEMM operands single fp16.
// ---------------------------------------------------------------------------
__device__ __align__(256) __half g_imgF[BATCH * FCIN];
__device__ __align__(256) __half g_W1F[FCIN * FCIN];     // [K,N]
__device__ __align__(256) __half g_Hf[BATCH * FCIN];     // lrelu out
__device__ __align__(256) __half g_W2F[FCIN * EMBED];    // [K,N]
__device__ __align__(256) __half g_Gf[BATCH * NASPAD];   // gathered, K-padded
__device__ __align__(256) __half g_ASF[NASPAD * EMBED];  // [Kpad,N], zero-padded
__device__ __align__(256) float g_F[BATCH * EMBED];
__device__ __align__(256) float g_V[BATCH * EMBED];

// ---------------------------------------------------------------------------
// PTX helpers
// ---------------------------------------------------------------------------
__device__ __forceinline__ uint32_t smem_u32(const void* p) {
    uint32_t a;
    asm("{ .reg .u64 t; cvta.to.shared.u64 t, %1; cvt.u32.u64 %0, t; }"
        : "=r"(a) : "l"(p));
    return a;
}
__device__ __forceinline__ void ldsm4(uint32_t* r, uint32_t addr) {
    asm volatile("ldmatrix.sync.aligned.m8n8.x4.shared.b16 {%0,%1,%2,%3}, [%4];"
        : "=r"(r[0]), "=r"(r[1]), "=r"(r[2]), "=r"(r[3]) : "r"(addr));
}
__device__ __forceinline__ void ldsm2t(uint32_t* r, uint32_t addr) {
    asm volatile("ldmatrix.sync.aligned.m8n8.x2.trans.shared.b16 {%0,%1}, [%2];"
        : "=r"(r[0]), "=r"(r[1]) : "r"(addr));
}
__device__ __forceinline__ void mma_f16(float* d, const uint32_t* a, const uint32_t* b) {
    asm volatile("mma.sync.aligned.m16n8k16.row.col.f32.f16.f16.f32 "
        "{%0,%1,%2,%3}, {%4,%5,%6,%7}, {%8,%9}, {%0,%1,%2,%3};"
        : "+f"(d[0]), "+f"(d[1]), "+f"(d[2]), "+f"(d[3])
        : "r"(a[0]), "r"(a[1]), "r"(a[2]), "r"(a[3]), "r"(b[0]), "r"(b[1]));
}
__device__ __forceinline__ void cpa16(uint32_t d, const void* s) {
    asm volatile("cp.async.cg.shared.global [%0], [%1], 16;" :: "r"(d), "l"(s));
}
#define CPA_COMMIT() asm volatile("cp.async.commit_group;" ::: "memory")
#define CPA_WAIT(n)  asm volatile("cp.async.wait_group %0;" :: "n"(n) : "memory")

__device__ __forceinline__ uint32_t pack_f16(__half a, __half b) {
    return (uint32_t)*(uint16_t*)&a | ((uint32_t)*(uint16_t*)&b << 16);
}

// ---------------------------------------------------------------------------
// Single-pass fp16 GEMM:  C = A·B (+bias) (+lrelu)
// A: [M,K] fp16. B: [K,N] fp16, fragments via ldmatrix.trans.
// 8 warps (BM/WM x BN/WN), BK=64, cp.async double-buffered, padded rows.
// EPI: 0 = +bias, lrelu, write fp16; 1 = +bias, fp32; 2 = fp32.
// ---------------------------------------------------------------------------
template<int BM, int BN, int BK, int WM, int WN, int EPI>
__global__ void __launch_bounds__(256)
gemm_f16(const __half* __restrict__ A, const __half* __restrict__ B,
         const float* __restrict__ bias, int K, int ldb, int ldc,
         float* __restrict__ Cf, __half* __restrict__ Ch)
{
    constexpr int SA = (BK + 8) * 2;
    constexpr int SB = (BN + 8) * 2;
    constexpr int OFF_A = 0;
    constexpr int OFF_B = BM * SA;
    constexpr int BUFB = BM * SA + BK * SB;
    constexpr int MI = WM / 16, NI = WN / 8;
    constexpr int KS = BK / 16;
    constexpr int AK8 = BK / 8;
    constexpr int BN8 = BN / 8;

    extern __shared__ __align__(128) char smem[];
    const uint32_t sb = smem_u32(smem);
    const int tid = threadIdx.x, wid = tid >> 5, lane = tid & 31;
    const int wm = wid % (BM / WM), wn = wid / (BM / WM);
    const int rowbase = blockIdx.y * BM, colbase = blockIdx.x * BN;

    const __half* srcA = A + (size_t)rowbase * K;
    const __half* srcB = B + colbase;

    float acc[MI][NI][4];
    #pragma unroll
    for (int i = 0; i < MI; i++)
        #pragma unroll
        for (int j = 0; j < NI; j++)
            #pragma unroll
            for (int q = 0; q < 4; q++) acc[i][j][q] = 0.f;

    const uint32_t aBase = (uint32_t)((wm * WM + (lane & 15)) * SA + (lane >> 4) * 16);
    const uint32_t bBase = (uint32_t)((lane & 15) * SB + (wn * WN) * 2);

    auto prefetch = [&](int chunk, int p) {
        const uint32_t tb = sb + p * BUFB;
        const int k0 = chunk * BK;
        #pragma unroll
        for (int i = tid; i < BM * AK8; i += 256) {
            int r = i / AK8, c = i % AK8;
            cpa16(tb + OFF_A + (uint32_t)(r * SA + c * 16),
                  srcA + (size_t)r * K + k0 + c * 8);
        }
        #pragma unroll
        for (int i = tid; i < BK * BN8; i += 256) {
            int r = i / BN8, c = i % BN8;
            cpa16(tb + OFF_B + (uint32_t)(r * SB + c * 16),
                  srcB + (size_t)(k0 + r) * ldb + c * 8);
        }
        CPA_COMMIT();
    };

    const int NC = K / BK;
    prefetch(0, 0);

    for (int c = 0; c < NC; c++) {
        const int p = c & 1;
        if (c + 1 < NC) { prefetch(c + 1, (c + 1) & 1); CPA_WAIT(1); }
        else            { CPA_WAIT(0); }
        __syncthreads();

        const uint32_t tb = sb + p * BUFB;
        #pragma unroll
        for (int ks = 0; ks < KS; ks++) {
            uint32_t aF[MI][4], bF[NI][2];
            #pragma unroll
            for (int mi = 0; mi < MI; mi++)
                ldsm4(aF[mi], tb + OFF_A + aBase + (uint32_t)(mi * 16 * SA + ks * 32));
            #pragma unroll
            for (int ni = 0; ni < NI; ni++)
                ldsm2t(bF[ni], tb + OFF_B + bBase + (uint32_t)(ks * 16 * SB + ni * 16));
            #pragma unroll
            for (int mi = 0; mi < MI; mi++)
                #pragma unroll
                for (int ni = 0; ni < NI; ni++)
                    mma_f16(acc[mi][ni], aF[mi], bF[ni]);
        }
        __syncthreads();
    }

    // Epilogue. Frag map: d0,d1 -> row lane>>2, cols (lane&3)*2,+1; d2,d3 -> +8 rows.
    const int r0 = rowbase + wm * WM + (lane >> 2);
    const int c0 = colbase + wn * WN + (lane & 3) * 2;
    #pragma unroll
    for (int mi = 0; mi < MI; mi++) {
        #pragma unroll
        for (int ni = 0; ni < NI; ni++) {
            const int cc = c0 + ni * 8;
            float b0 = 0.f, b1 = 0.f;
            if (EPI == 0 || EPI == 1) { b0 = __ldg(&bias[cc]); b1 = __ldg(&bias[cc + 1]); }
            #pragma unroll
            for (int h = 0; h < 2; h++) {
                const int rr = r0 + mi * 16 + h * 8;
                float v0 = acc[mi][ni][2 * h]     + b0;
                float v1 = acc[mi][ni][2 * h + 1] + b1;
                if (EPI == 0) {
                    v0 = v0 > 0.f ? v0 : 0.01f * v0;
                    v1 = v1 > 0.f ? v1 : 0.01f * v1;
                    *(uint32_t*)(Ch + (size_t)rr * ldc + cc) =
                        pack_f16(__float2half_rn(v0), __float2half_rn(v1));
                } else {
                    *(float2*)(Cf + (size_t)rr * ldc + cc) = make_float2(v0, v1);
                }
            }
        }
    }
}

// ---------------------------------------------------------------------------
// fp32 -> fp16 cast with optional zero suffix; 8 elems/thread, grid-stride x2.
// Indices i in [valid8, total8) write zeros.
// ---------------------------------------------------------------------------
__global__ void __launch_bounds__(256)
cast8_half(const float* __restrict__ in, __half* __restrict__ o,
           int total8, int valid8)
{
    const int t = blockIdx.x * 256 + threadIdx.x;
    const int NT = gridDim.x * 256;
    #pragma unroll
    for (int k = 0; k < 2; k++) {
        int i = t + k * NT;
        if (i < total8) {
            uint4 r = make_uint4(0, 0, 0, 0);
            if (i < valid8) {
                float4 a = ((const float4*)in)[2 * i];
                float4 b = ((const float4*)in)[2 * i + 1];
                r = make_uint4(
                    pack_f16(__float2half_rn(a.x), __float2half_rn(a.y)),
                    pack_f16(__float2half_rn(a.z), __float2half_rn(a.w)),
                    pack_f16(__float2half_rn(b.x), __float2half_rn(b.y)),
                    pack_f16(__float2half_rn(b.z), __float2half_rn(b.w)));
            }
            ((uint4*)o)[i] = r;
        }
    }
}

// Gather brand rows -> fp16 single, pad cols to NASPAD
__global__ void __launch_bounds__(256)
gather_cast(const float* __restrict__ emb, const int* __restrict__ idx,
            __half* __restrict__ o)
{
    const int b = blockIdx.x;
    int row = idx[b];
    row = row < 0 ? 0 : (row >= NBRANDS ? NBRANDS - 1 : row);
    const float4* src = (const float4*)(emb + (size_t)row * NASPECT);
    for (int j = threadIdx.x; j < NASPAD / 4; j += 256) {
        uint2 p = make_uint2(0, 0);
        if (j < NASPECT / 4) {
            float4 v = src[j];
            p = make_uint2(pack_f16(__float2half_rn(v.x), __float2half_rn(v.y)),
                           pack_f16(__float2half_rn(v.z), __float2half_rn(v.w)));
        }
        ((uint2*)(o + (size_t)b * NASPAD))[j] = p;
    }
}

// out[b] = dot(g_F[b,:], g_V[b,:]) / NASPECT
__global__ void __launch_bounds__(256)
final_dot(float* __restrict__ out)
{
    const int b = blockIdx.x;
    const float* f = g_F + (size_t)b * EMBED;
    const float* v = g_V + (size_t)b * EMBED;
    float s = 0.f;
    for (int i = threadIdx.x; i < EMBED; i += 256)
        s = fmaf(f[i], v[i], s);
    #pragma unroll
    for (int off = 16; off > 0; off >>= 1)
        s += __shfl_xor_sync(0xFFFFFFFFu, s, off);
    __shared__ float red[8];
    if ((threadIdx.x & 31) == 0) red[threadIdx.x >> 5] = s;
    __syncthreads();
    if (threadIdx.x < 8) {
        s = red[threadIdx.x];
        #pragma unroll
        for (int off = 4; off > 0; off >>= 1)
            s += __shfl_xor_sync(0xFFu, s, off);
        if (threadIdx.x == 0) out[b] = s * (1.0f / (float)NASPECT);
    }
}

// ---------------------------------------------------------------------------
#define SM_G1 (2 * (128 * (64 + 8) * 2 + 64 * (128 + 8) * 2))   // 71680
#define SM_G2 (2 * (64 * (64 + 8) * 2 + 64 * (64 + 8) * 2))     // 36864
#define G8(n8) (((n8) + 2 * 256 - 1) / (2 * 256))

extern "C" void kernel_launch(void* const* d_in, const int* in_sizes, int n_in,
                              void* d_out, int out_size)
{
    const float* image     = (const float*)d_in[0];
    const int*   brand     = (const int*)d_in[1];
    const float* W1        = (const float*)d_in[2];
    const float* b1        = (const float*)d_in[3];
    const float* W2        = (const float*)d_in[4];
    const float* b2        = (const float*)d_in[5];
    const float* brand_emb = (const float*)d_in[6];
    const float* aspects   = (const float*)d_in[7];
    float*       out       = (float*)d_out;

    static bool init = false;
    static __half *pImgF, *pW1F, *pHf, *pW2F, *pGf, *pASF;
    static float *pF, *pV;
    if (!init) {
        cudaGetSymbolAddress((void**)&pImgF, g_imgF);
        cudaGetSymbolAddress((void**)&pW1F,  g_W1F);
        cudaGetSymbolAddress((void**)&pHf,   g_Hf);
        cudaGetSymbolAddress((void**)&pW2F,  g_W2F);
        cudaGetSymbolAddress((void**)&pGf,   g_Gf);
        cudaGetSymbolAddress((void**)&pASF,  g_ASF);
        cudaGetSymbolAddress((void**)&pF,    g_F);
        cudaGetSymbolAddress((void**)&pV,    g_V);
        cudaFuncSetAttribute((const void*)gemm_f16<128,128,64,64,32,0>,
                             cudaFuncAttributeMaxDynamicSharedMemorySize, SM_G1);
        cudaFuncSetAttribute((const void*)gemm_f16<64,64,64,32,16,2>,
                             cudaFuncAttributeMaxDynamicSharedMemorySize, SM_G2);
        cudaFuncSetAttribute((const void*)gemm_f16<64,64,64,32,16,1>,
                             cudaFuncAttributeMaxDynamicSharedMemorySize, SM_G2);
        init = true;
    }

    // Operand conversions (all plain casts now)
    cast8_half<<<G8(BATCH * FCIN / 8), 256>>>(
        image, pImgF, BATCH * FCIN / 8, BATCH * FCIN / 8);
    cast8_half<<<G8(FCIN * FCIN / 8), 256>>>(
        W1, pW1F, FCIN * FCIN / 8, FCIN * FCIN / 8);
    cast8_half<<<G8(FCIN * EMBED / 8), 256>>>(
        W2, pW2F, FCIN * EMBED / 8, FCIN * EMBED / 8);
    cast8_half<<<G8(NASPAD * EMBED / 8), 256>>>(
        aspects, pASF, NASPAD * EMBED / 8, NASPECT * EMBED / 8);
    gather_cast<<<BATCH, 256>>>(brand_emb, brand, pGf);

    // GEMM1: H = lrelu(image @ W1 + b1) -> fp16
    gemm_f16<128,128,64,64,32,0><<<dim3(FCIN / 128, BATCH / 128), 256, SM_G1>>>(
        pImgF, pW1F, b1, FCIN, FCIN, FCIN, nullptr, pHf);

    // GEMM3: V = gather(brand_emb) @ aspects -> fp32
    gemm_f16<64,64,64,32,16,2><<<dim3(EMBED / 64, BATCH / 64), 256, SM_G2>>>(
        pGf, pASF, nullptr, NASPAD, EMBED, EMBED, pV, nullptr);

    // GEMM2: F = H @ W2 + b2 -> fp32
    gemm_f16<64,64,64,32,16,1><<<dim3(EMBED / 64, BATCH / 64), 256, SM_G2>>>(
        pHf, pW2F, b2, FCIN, EMBED, EMBED, pF, nullptr);

    final_dot<<<BATCH, 256>>>(out);
}

// round 14
// speedup vs baseline: 1.7673x; 1.0396x over previous
#include <cuda_runtime.h>
#include <cuda_bf16.h>
#include <cuda_fp16.h>
#include <cstdint>

#define BATCH   512
#define FCIN    4096
#define EMBED   1024
#define NASPECT 2000
#define NASPAD  2048
#define NBRANDS 10000

// ---------------------------------------------------------------------------
// Scratch. All GEMM operands single fp16.
// ---------------------------------------------------------------------------
__device__ __align__(256) __half g_imgF[BATCH * FCIN];
__device__ __align__(256) __half g_W1F[FCIN * FCIN];     // [K,N]
__device__ __align__(256) __half g_Hf[BATCH * FCIN];     // lrelu out
__device__ __align__(256) __half g_W2F[FCIN * EMBED];    // [K,N]
__device__ __align__(256) __half g_Gf[BATCH * NASPAD];   // gathered, K-padded
__device__ __align__(256) __half g_ASF[NASPAD * EMBED];  // [Kpad,N], zero-padded
__device__ __align__(256) float g_F[BATCH * EMBED];
__device__ __align__(256) float g_V[BATCH * EMBED];

// ---------------------------------------------------------------------------
// PTX helpers
// ---------------------------------------------------------------------------
__device__ __forceinline__ uint32_t smem_u32(const void* p) {
    uint32_t a;
    asm("{ .reg .u64 t; cvta.to.shared.u64 t, %1; cvt.u32.u64 %0, t; }"
        : "=r"(a) : "l"(p));
    return a;
}
__device__ __forceinline__ void ldsm4(uint32_t* r, uint32_t addr) {
    asm volatile("ldmatrix.sync.aligned.m8n8.x4.shared.b16 {%0,%1,%2,%3}, [%4];"
        : "=r"(r[0]), "=r"(r[1]), "=r"(r[2]), "=r"(r[3]) : "r"(addr));
}
__device__ __forceinline__ void ldsm2t(uint32_t* r, uint32_t addr) {
    asm volatile("ldmatrix.sync.aligned.m8n8.x2.trans.shared.b16 {%0,%1}, [%2];"
        : "=r"(r[0]), "=r"(r[1]) : "r"(addr));
}
__device__ __forceinline__ void mma_f16(float* d, const uint32_t* a, const uint32_t* b) {
    asm volatile("mma.sync.aligned.m16n8k16.row.col.f32.f16.f16.f32 "
        "{%0,%1,%2,%3}, {%4,%5,%6,%7}, {%8,%9}, {%0,%1,%2,%3};"
        : "+f"(d[0]), "+f"(d[1]), "+f"(d[2]), "+f"(d[3])
        : "r"(a[0]), "r"(a[1]), "r"(a[2]), "r"(a[3]), "r"(b[0]), "r"(b[1]));
}
__device__ __forceinline__ void cpa16(uint32_t d, const void* s) {
    asm volatile("cp.async.cg.shared.global [%0], [%1], 16;" :: "r"(d), "l"(s));
}
#define CPA_COMMIT() asm volatile("cp.async.commit_group;" ::: "memory")
#define CPA_WAIT(n)  asm volatile("cp.async.wait_group %0;" :: "n"(n) : "memory")

__device__ __forceinline__ uint32_t pack_f16(__half a, __half b) {
    return (uint32_t)*(uint16_t*)&a | ((uint32_t)*(uint16_t*)&b << 16);
}

// ---------------------------------------------------------------------------
// Single-pass fp16 GEMM:  C = A·B (+bias) (+lrelu)   (validated R13 core)
// EPI: 0 = +bias, lrelu, write fp16; 1 = +bias, fp32; 2 = fp32.
// ---------------------------------------------------------------------------
template<int BM, int BN, int BK, int WM, int WN, int EPI>
__global__ void __launch_bounds__(256)
gemm_f16(const __half* __restrict__ A, const __half* __restrict__ B,
         const float* __restrict__ bias, int K, int ldb, int ldc,
         float* __restrict__ Cf, __half* __restrict__ Ch)
{
    constexpr int SA = (BK + 8) * 2;
    constexpr int SB = (BN + 8) * 2;
    constexpr int OFF_A = 0;
    constexpr int OFF_B = BM * SA;
    constexpr int BUFB = BM * SA + BK * SB;
    constexpr int MI = WM / 16, NI = WN / 8;
    constexpr int KS = BK / 16;
    constexpr int AK8 = BK / 8;
    constexpr int BN8 = BN / 8;

    extern __shared__ __align__(128) char smem[];
    const uint32_t sb = smem_u32(smem);
    const int tid = threadIdx.x, wid = tid >> 5, lane = tid & 31;
    const int wm = wid % (BM / WM), wn = wid / (BM / WM);
    const int rowbase = blockIdx.y * BM, colbase = blockIdx.x * BN;

    const __half* srcA = A + (size_t)rowbase * K;
    const __half* srcB = B + colbase;

    float acc[MI][NI][4];
    #pragma unroll
    for (int i = 0; i < MI; i++)
        #pragma unroll
        for (int j = 0; j < NI; j++)
            #pragma unroll
            for (int q = 0; q < 4; q++) acc[i][j][q] = 0.f;

    const uint32_t aBase = (uint32_t)((wm * WM + (lane & 15)) * SA + (lane >> 4) * 16);
    const uint32_t bBase = (uint32_t)((lane & 15) * SB + (wn * WN) * 2);

    auto prefetch = [&](int chunk, int p) {
        const uint32_t tb = sb + p * BUFB;
        const int k0 = chunk * BK;
        #pragma unroll
        for (int i = tid; i < BM * AK8; i += 256) {
            int r = i / AK8, c = i % AK8;
            cpa16(tb + OFF_A + (uint32_t)(r * SA + c * 16),
                  srcA + (size_t)r * K + k0 + c * 8);
        }
        #pragma unroll
        for (int i = tid; i < BK * BN8; i += 256) {
            int r = i / BN8, c = i % BN8;
            cpa16(tb + OFF_B + (uint32_t)(r * SB + c * 16),
                  srcB + (size_t)(k0 + r) * ldb + c * 8);
        }
        CPA_COMMIT();
    };

    const int NC = K / BK;
    prefetch(0, 0);

    for (int c = 0; c < NC; c++) {
        const int p = c & 1;
        if (c + 1 < NC) { prefetch(c + 1, (c + 1) & 1); CPA_WAIT(1); }
        else            { CPA_WAIT(0); }
        __syncthreads();

        const uint32_t tb = sb + p * BUFB;
        #pragma unroll
        for (int ks = 0; ks < KS; ks++) {
            uint32_t aF[MI][4], bF[NI][2];
            #pragma unroll
            for (int mi = 0; mi < MI; mi++)
                ldsm4(aF[mi], tb + OFF_A + aBase + (uint32_t)(mi * 16 * SA + ks * 32));
            #pragma unroll
            for (int ni = 0; ni < NI; ni++)
                ldsm2t(bF[ni], tb + OFF_B + bBase + (uint32_t)(ks * 16 * SB + ni * 16));
            #pragma unroll
            for (int mi = 0; mi < MI; mi++)
                #pragma unroll
                for (int ni = 0; ni < NI; ni++)
                    mma_f16(acc[mi][ni], aF[mi], bF[ni]);
        }
        __syncthreads();
    }

    const int r0 = rowbase + wm * WM + (lane >> 2);
    const int c0 = colbase + wn * WN + (lane & 3) * 2;
    #pragma unroll
    for (int mi = 0; mi < MI; mi++) {
        #pragma unroll
        for (int ni = 0; ni < NI; ni++) {
            const int cc = c0 + ni * 8;
            float b0 = 0.f, b1 = 0.f;
            if (EPI == 0 || EPI == 1) { b0 = __ldg(&bias[cc]); b1 = __ldg(&bias[cc + 1]); }
            #pragma unroll
            for (int h = 0; h < 2; h++) {
                const int rr = r0 + mi * 16 + h * 8;
                float v0 = acc[mi][ni][2 * h]     + b0;
                float v1 = acc[mi][ni][2 * h + 1] + b1;
                if (EPI == 0) {
                    v0 = v0 > 0.f ? v0 : 0.01f * v0;
                    v1 = v1 > 0.f ? v1 : 0.01f * v1;
                    *(uint32_t*)(Ch + (size_t)rr * ldc + cc) =
                        pack_f16(__float2half_rn(v0), __float2half_rn(v1));
                } else {
                    *(float2*)(Cf + (size_t)rr * ldc + cc) = make_float2(v0, v1);
                }
            }
        }
    }
}

// ---------------------------------------------------------------------------
// prep_all: ALL operand conversions in one launch.
// Unified index space of 8-element (uint4-out) work items:
//   [0, S0)       image cast        (262144 items)
//   [S0, S1)      W1 cast           (2097152)
//   [S1, S2)      W2 cast           (524288)
//   [S2, S3)      aspects cast+pad  (262144; valid 256000)
//   [S3, S4)      brand gather+pad  (131072: 512 rows x 256 items)
// ---------------------------------------------------------------------------
#define PREP_S0 (BATCH * FCIN / 8)                    // 262144
#define PREP_S1 (PREP_S0 + FCIN * FCIN / 8)           // +2097152
#define PREP_S2 (PREP_S1 + FCIN * EMBED / 8)          // +524288
#define PREP_S3 (PREP_S2 + NASPAD * EMBED / 8)        // +262144
#define PREP_S4 (PREP_S3 + BATCH * NASPAD / 8)        // +131072
#define ASP_VALID8 (NASPECT * EMBED / 8)              // 256000
#define GITEMS_PER_ROW (NASPAD / 8)                   // 256
#define GVALID_PER_ROW (NASPECT / 8)                  // 250

__device__ __forceinline__ uint4 cast8(const float* __restrict__ src, int i8)
{
    float4 a = ((const float4*)src)[2 * i8];
    float4 b = ((const float4*)src)[2 * i8 + 1];
    return make_uint4(pack_f16(__float2half_rn(a.x), __float2half_rn(a.y)),
                      pack_f16(__float2half_rn(a.z), __float2half_rn(a.w)),
                      pack_f16(__float2half_rn(b.x), __float2half_rn(b.y)),
                      pack_f16(__float2half_rn(b.z), __float2half_rn(b.w)));
}

__global__ void __launch_bounds__(256)
prep_all(const float* __restrict__ image, const float* __restrict__ W1,
         const float* __restrict__ W2, const float* __restrict__ aspects,
         const float* __restrict__ emb, const int* __restrict__ idx,
         __half* __restrict__ oImg, __half* __restrict__ oW1,
         __half* __restrict__ oW2, __half* __restrict__ oAsp,
         __half* __restrict__ oG)
{
    const int NT = gridDim.x * 256;
    for (int i = blockIdx.x * 256 + threadIdx.x; i < PREP_S4; i += NT) {
        if (i < PREP_S0) {
            ((uint4*)oImg)[i] = cast8(image, i);
        } else if (i < PREP_S1) {
            int j = i - PREP_S0;
            ((uint4*)oW1)[j] = cast8(W1, j);
        } else if (i < PREP_S2) {
            int j = i - PREP_S1;
            ((uint4*)oW2)[j] = cast8(W2, j);
        } else if (i < PREP_S3) {
            int j = i - PREP_S2;
            uint4 r = make_uint4(0, 0, 0, 0);
            if (j < ASP_VALID8) r = cast8(aspects, j);
            ((uint4*)oAsp)[j] = r;
        } else {
            int j = i - PREP_S3;
            int row = j / GITEMS_PER_ROW, c8 = j % GITEMS_PER_ROW;
            uint4 r = make_uint4(0, 0, 0, 0);
            if (c8 < GVALID_PER_ROW) {
                int src = idx[row];
                src = src < 0 ? 0 : (src >= NBRANDS ? NBRANDS - 1 : src);
                const float4* s = (const float4*)(emb + (size_t)src * NASPECT + c8 * 8);
                float4 a = s[0], b = s[1];
                r = make_uint4(pack_f16(__float2half_rn(a.x), __float2half_rn(a.y)),
                               pack_f16(__float2half_rn(a.z), __float2half_rn(a.w)),
                               pack_f16(__float2half_rn(b.x), __float2half_rn(b.y)),
                               pack_f16(__float2half_rn(b.z), __float2half_rn(b.w)));
            }
            ((uint4*)oG)[j] = r;
        }
    }
}

// ---------------------------------------------------------------------------
// out[b] = dot(g_F[b,:], g_V[b,:]) / NASPECT  (float4 vectorized, 1 iter/thread)
// ---------------------------------------------------------------------------
__global__ void __launch_bounds__(256)
final_dot(float* __restrict__ out)
{
    const int b = blockIdx.x;
    const float4* f = (const float4*)(g_F + (size_t)b * EMBED);
    const float4* v = (const float4*)(g_V + (size_t)b * EMBED);
    float4 a = f[threadIdx.x], c = v[threadIdx.x];
    float s = a.x * c.x + a.y * c.y + a.z * c.z + a.w * c.w;
    #pragma unroll
    for (int off = 16; off > 0; off >>= 1)
        s += __shfl_xor_sync(0xFFFFFFFFu, s, off);
    __shared__ float red[8];
    if ((threadIdx.x & 31) == 0) red[threadIdx.x >> 5] = s;
    __syncthreads();
    if (threadIdx.x < 8) {
        s = red[threadIdx.x];
        #pragma unroll
        for (int off = 4; off > 0; off >>= 1)
            s += __shfl_xor_sync(0xFFu, s, off);
        if (threadIdx.x == 0) out[b] = s * (1.0f / (float)NASPECT);
    }
}

// ---------------------------------------------------------------------------
#define SM_G1 (2 * (128 * (64 + 8) * 2 + 64 * (128 + 8) * 2))   // 71680
#define SM_G2 (2 * (64 * (64 + 8) * 2 + 64 * (64 + 8) * 2))     // 36864

extern "C" void kernel_launch(void* const* d_in, const int* in_sizes, int n_in,
                              void* d_out, int out_size)
{
    const float* image     = (const float*)d_in[0];
    const int*   brand     = (const int*)d_in[1];
    const float* W1        = (const float*)d_in[2];
    const float* b1        = (const float*)d_in[3];
    const float* W2        = (const float*)d_in[4];
    const float* b2        = (const float*)d_in[5];
    const float* brand_emb = (const float*)d_in[6];
    const float* aspects   = (const float*)d_in[7];
    float*       out       = (float*)d_out;

    static bool init = false;
    static __half *pImgF, *pW1F, *pHf, *pW2F, *pGf, *pASF;
    static float *pF, *pV;
    if (!init) {
        cudaGetSymbolAddress((void**)&pImgF, g_imgF);
        cudaGetSymbolAddress((void**)&pW1F,  g_W1F);
        cudaGetSymbolAddress((void**)&pHf,   g_Hf);
        cudaGetSymbolAddress((void**)&pW2F,  g_W2F);
        cudaGetSymbolAddress((void**)&pGf,   g_Gf);
        cudaGetSymbolAddress((void**)&pASF,  g_ASF);
        cudaGetSymbolAddress((void**)&pF,    g_F);
        cudaGetSymbolAddress((void**)&pV,    g_V);
        cudaFuncSetAttribute((const void*)gemm_f16<128,128,64,64,32,0>,
                             cudaFuncAttributeMaxDynamicSharedMemorySize, SM_G1);
        cudaFuncSetAttribute((const void*)gemm_f16<64,64,64,32,16,2>,
                             cudaFuncAttributeMaxDynamicSharedMemorySize, SM_G2);
        cudaFuncSetAttribute((const void*)gemm_f16<64,64,64,32,16,1>,
                             cudaFuncAttributeMaxDynamicSharedMemorySize, SM_G2);
        init = true;
    }

    // All operand conversions in one launch (4096 CTAs, grid-stride)
    prep_all<<<4096, 256>>>(image, W1, W2, aspects, brand_emb, brand,
                            pImgF, pW1F, pW2F, pASF, pGf);

    // GEMM1: H = lrelu(image @ W1 + b1) -> fp16
    gemm_f16<128,128,64,64,32,0><<<dim3(FCIN / 128, BATCH / 128), 256, SM_G1>>>(
        pImgF, pW1F, b1, FCIN, FCIN, FCIN, nullptr, pHf);

    // GEMM3: V = gather(brand_emb) @ aspects -> fp32
    gemm_f16<64,64,64,32,16,2><<<dim3(EMBED / 64, BATCH / 64), 256, SM_G2>>>(
        pGf, pASF, nullptr, NASPAD, EMBED, EMBED, pV, nullptr);

    // GEMM2: F = H @ W2 + b2 -> fp32
    gemm_f16<64,64,64,32,16,1><<<dim3(EMBED / 64, BATCH / 64), 256, SM_G2>>>(
        pHf, pW2F, b2, FCIN, EMBED, EMBED, pF, nullptr);

    final_dot<<<BATCH, 256>>>(out);
}

// round 15
// speedup vs baseline: 2.0299x; 1.1486x over previous
#include <cuda_runtime.h>
#include <cuda_bf16.h>
#include <cuda_fp16.h>
#include <cstdint>

#define BATCH   512
#define FCIN    4096
#define EMBED   1024
#define NASPECT 2000
#define NASPAD  2048
#define NBRANDS 10000

// ---------------------------------------------------------------------------
// Scratch
// ---------------------------------------------------------------------------
__device__ __align__(256) __half g_imgF[BATCH * FCIN];
__device__ __align__(256) __half g_W1F[FCIN * FCIN];       // [K,N]
__device__ __align__(256) float  g_Hp[2 * BATCH * FCIN];   // GEMM1 partials
__device__ __align__(256) __half g_Hf[BATCH * FCIN];       // lrelu out
__device__ __align__(256) __half g_W2F[FCIN * EMBED];      // [K,N]
__device__ __align__(256) __half g_Gf[BATCH * NASPAD];     // gathered, padded
__device__ __align__(256) __half g_ASF[NASPAD * EMBED];    // [Kpad,N], padded
__device__ __align__(256) float  g_Fp[4 * BATCH * EMBED];  // GEMM2 partials
__device__ __align__(256) float  g_Vp[2 * BATCH * EMBED];  // GEMM3 partials

// ---------------------------------------------------------------------------
// PTX helpers
// ---------------------------------------------------------------------------
__device__ __forceinline__ uint32_t smem_u32(const void* p) {
    uint32_t a;
    asm("{ .reg .u64 t; cvta.to.shared.u64 t, %1; cvt.u32.u64 %0, t; }"
        : "=r"(a) : "l"(p));
    return a;
}
__device__ __forceinline__ void ldsm4(uint32_t* r, uint32_t addr) {
    asm volatile("ldmatrix.sync.aligned.m8n8.x4.shared.b16 {%0,%1,%2,%3}, [%4];"
        : "=r"(r[0]), "=r"(r[1]), "=r"(r[2]), "=r"(r[3]) : "r"(addr));
}
__device__ __forceinline__ void ldsm2t(uint32_t* r, uint32_t addr) {
    asm volatile("ldmatrix.sync.aligned.m8n8.x2.trans.shared.b16 {%0,%1}, [%2];"
        : "=r"(r[0]), "=r"(r[1]) : "r"(addr));
}
__device__ __forceinline__ void mma_f16(float* d, const uint32_t* a, const uint32_t* b) {
    asm volatile("mma.sync.aligned.m16n8k16.row.col.f32.f16.f16.f32 "
        "{%0,%1,%2,%3}, {%4,%5,%6,%7}, {%8,%9}, {%0,%1,%2,%3};"
        : "+f"(d[0]), "+f"(d[1]), "+f"(d[2]), "+f"(d[3])
        : "r"(a[0]), "r"(a[1]), "r"(a[2]), "r"(a[3]), "r"(b[0]), "r"(b[1]));
}
__device__ __forceinline__ void cpa16(uint32_t d, const void* s) {
    asm volatile("cp.async.cg.shared.global [%0], [%1], 16;" :: "r"(d), "l"(s));
}
#define CPA_COMMIT() asm volatile("cp.async.commit_group;" ::: "memory")
#define CPA_WAIT(n)  asm volatile("cp.async.wait_group %0;" :: "n"(n) : "memory")

__device__ __forceinline__ uint32_t pack_f16(__half a, __half b) {
    return (uint32_t)*(uint16_t*)&a | ((uint32_t)*(uint16_t*)&b << 16);
}

// ---------------------------------------------------------------------------
// GEMM core macro body (validated R13 loop), parameterized by constexprs in
// the enclosing scope: BM,BN,BK,WM,WN and runtime srcA,srcB,lda,ldb,NC.
// Produces acc[MI][NI][4]; caller provides epilogue.
// ---------------------------------------------------------------------------
#define GEMM_CORE(BM, BN, BK, WM, WN, srcA, srcB, lda, ldb, NC, acc)           \
    constexpr int SA = (BK + 8) * 2;                                           \
    constexpr int SB = (BN + 8) * 2;                                           \
    constexpr int OFF_A = 0;                                                   \
    constexpr int OFF_B = BM * SA;                                             \
    constexpr int BUFB = BM * SA + BK * SB;                                    \
    constexpr int MI = WM / 16, NI = WN / 8;                                   \
    constexpr int KS = BK / 16;                                                \
    constexpr int AK8 = BK / 8;                                                \
    constexpr int BN8 = BN / 8;                                                \
    extern __shared__ __align__(128) char smem[];                              \
    const uint32_t sbm = smem_u32(smem);                                       \
    const int tid = threadIdx.x, wid = tid >> 5, lane = tid & 31;              \
    const int wm = wid % (BM / WM), wn = wid / (BM / WM);                      \
    _Pragma("unroll")                                                          \
    for (int i = 0; i < MI; i++)                                               \
        _Pragma("unroll")                                                      \
        for (int j = 0; j < NI; j++)                                           \
            _Pragma("unroll")                                                  \
            for (int q = 0; q < 4; q++) acc[i][j][q] = 0.f;                    \
    const uint32_t aBase = (uint32_t)((wm * WM + (lane & 15)) * SA + (lane >> 4) * 16); \
    const uint32_t bBase = (uint32_t)((lane & 15) * SB + (wn * WN) * 2);       \
    auto prefetch = [&](int chunk, int p) {                                    \
        const uint32_t tb = sbm + p * BUFB;                                    \
        const int k0 = chunk * BK;                                             \
        _Pragma("unroll")                                                      \
        for (int i = tid; i < BM * AK8; i += 256) {                            \
            int r = i / AK8, c = i % AK8;                                      \
            cpa16(tb + OFF_A + (uint32_t)(r * SA + c * 16),                    \
                  srcA + (size_t)r * lda + k0 + c * 8);                        \
        }                                                                      \
        _Pragma("unroll")                                                      \
        for (int i = tid; i < BK * BN8; i += 256) {                            \
            int r = i / BN8, c = i % BN8;                                      \
            cpa16(tb + OFF_B + (uint32_t)(r * SB + c * 16),                    \
                  srcB + (size_t)(k0 + r) * ldb + c * 8);                      \
        }                                                                      \
        CPA_COMMIT();                                                          \
    };                                                                         \
    prefetch(0, 0);                                                            \
    for (int c = 0; c < NC; c++) {                                             \
        const int p = c & 1;                                                   \
        if (c + 1 < NC) { prefetch(c + 1, (c + 1) & 1); CPA_WAIT(1); }         \
        else            { CPA_WAIT(0); }                                       \
        __syncthreads();                                                       \
        const uint32_t tb = sbm + p * BUFB;                                    \
        _Pragma("unroll")                                                      \
        for (int ks = 0; ks < KS; ks++) {                                      \
            uint32_t aF[MI][4], bF[NI][2];                                     \
            _Pragma("unroll")                                                  \
            for (int mi = 0; mi < MI; mi++)                                    \
                ldsm4(aF[mi], tb + OFF_A + aBase + (uint32_t)(mi * 16 * SA + ks * 32)); \
            _Pragma("unroll")                                                  \
            for (int ni = 0; ni < NI; ni++)                                    \
                ldsm2t(bF[ni], tb + OFF_B + bBase + (uint32_t)(ks * 16 * SB + ni * 16)); \
            _Pragma("unroll")                                                  \
            for (int mi = 0; mi < MI; mi++)                                    \
                _Pragma("unroll")                                              \
                for (int ni = 0; ni < NI; ni++)                                \
                    mma_f16(acc[mi][ni], aF[mi], bF[ni]);                      \
        }                                                                      \
        __syncthreads();                                                       \
    }

// ---------------------------------------------------------------------------
// GEMM1 split-K2: partial z = image[:, z*2048:(z+1)*2048] @ W1[z*2048:..., :]
// 128x128 tile, grid (32, 4, 2). Raw fp32 partial to g_Hp[z].
// ---------------------------------------------------------------------------
__global__ void __launch_bounds__(256)
gemm1_split()
{
    const int z = blockIdx.z;
    const int rowbase = blockIdx.y * 128, colbase = blockIdx.x * 128;
    const int kb = z * 2048;
    const __half* srcA = g_imgF + (size_t)rowbase * FCIN + kb;
    const __half* srcB = g_W1F + (size_t)kb * FCIN + colbase;
    float* Cout = g_Hp + (size_t)z * BATCH * FCIN;

    float acc[4][4][4];
    GEMM_CORE(128, 128, 64, 64, 32, srcA, srcB, FCIN, FCIN, 32, acc)

    const int r0 = rowbase + wm * 64 + (lane >> 2);
    const int c0 = colbase + wn * 32 + (lane & 3) * 2;
    #pragma unroll
    for (int mi = 0; mi < 4; mi++)
        #pragma unroll
        for (int ni = 0; ni < 4; ni++)
            #pragma unroll
            for (int h = 0; h < 2; h++) {
                const int rr = r0 + mi * 16 + h * 8;
                *(float2*)(Cout + (size_t)rr * FCIN + c0 + ni * 8) =
                    make_float2(acc[mi][ni][2 * h], acc[mi][ni][2 * h + 1]);
            }
}

// ---------------------------------------------------------------------------
// Fused GEMM2 (split-K4) + GEMM3 (split-K2): 64x64 tiles, grid (16, 8, 6).
// z in [0,4): F partial z (A=g_Hf K-slice, B=g_W2F slice)
// z in [4,6): V partial z-4 (A=g_Gf K-slice, B=g_ASF slice)
// K_len = 1024 uniform. Raw fp32 partials.
// ---------------------------------------------------------------------------
__global__ void __launch_bounds__(256)
gemm23_split()
{
    const int z = blockIdx.z;
    const int rowbase = blockIdx.y * 64, colbase = blockIdx.x * 64;
    const __half* srcA;
    const __half* srcB;
    float* Cout;
    int lda;
    if (z < 4) {
        lda  = FCIN;
        srcA = g_Hf + (size_t)rowbase * FCIN + z * 1024;
        srcB = g_W2F + (size_t)z * 1024 * EMBED + colbase;
        Cout = g_Fp + (size_t)z * BATCH * EMBED;
    } else {
        const int zz = z - 4;
        lda  = NASPAD;
        srcA = g_Gf + (size_t)rowbase * NASPAD + zz * 1024;
        srcB = g_ASF + (size_t)zz * 1024 * EMBED + colbase;
        Cout = g_Vp + (size_t)zz * BATCH * EMBED;
    }

    float acc[2][2][4];
    GEMM_CORE(64, 64, 64, 32, 16, srcA, srcB, lda, EMBED, 16, acc)

    const int r0 = rowbase + wm * 32 + (lane >> 2);
    const int c0 = colbase + wn * 16 + (lane & 3) * 2;
    #pragma unroll
    for (int mi = 0; mi < 2; mi++)
        #pragma unroll
        for (int ni = 0; ni < 2; ni++)
            #pragma unroll
            for (int h = 0; h < 2; h++) {
                const int rr = r0 + mi * 16 + h * 8;
                *(float2*)(Cout + (size_t)rr * EMBED + c0 + ni * 8) =
                    make_float2(acc[mi][ni][2 * h], acc[mi][ni][2 * h + 1]);
            }
}

// ---------------------------------------------------------------------------
// prep_all: all operand conversions in one launch (validated R14)
// ---------------------------------------------------------------------------
#define PREP_S0 (BATCH * FCIN / 8)
#define PREP_S1 (PREP_S0 + FCIN * FCIN / 8)
#define PREP_S2 (PREP_S1 + FCIN * EMBED / 8)
#define PREP_S3 (PREP_S2 + NASPAD * EMBED / 8)
#define PREP_S4 (PREP_S3 + BATCH * NASPAD / 8)
#define ASP_VALID8 (NASPECT * EMBED / 8)
#define GITEMS_PER_ROW (NASPAD / 8)
#define GVALID_PER_ROW (NASPECT / 8)

__device__ __forceinline__ uint4 cast8(const float* __restrict__ src, int i8)
{
    float4 a = ((const float4*)src)[2 * i8];
    float4 b = ((const float4*)src)[2 * i8 + 1];
    return make_uint4(pack_f16(__float2half_rn(a.x), __float2half_rn(a.y)),
                      pack_f16(__float2half_rn(a.z), __float2half_rn(a.w)),
                      pack_f16(__float2half_rn(b.x), __float2half_rn(b.y)),
                      pack_f16(__float2half_rn(b.z), __float2half_rn(b.w)));
}

__global__ void __launch_bounds__(256)
prep_all(const float* __restrict__ image, const float* __restrict__ W1,
         const float* __restrict__ W2, const float* __restrict__ aspects,
         const float* __restrict__ emb, const int* __restrict__ idx)
{
    const int NT = gridDim.x * 256;
    for (int i = blockIdx.x * 256 + threadIdx.x; i < PREP_S4; i += NT) {
        if (i < PREP_S0) {
            ((uint4*)g_imgF)[i] = cast8(image, i);
        } else if (i < PREP_S1) {
            int j = i - PREP_S0;
            ((uint4*)g_W1F)[j] = cast8(W1, j);
        } else if (i < PREP_S2) {
            int j = i - PREP_S1;
            ((uint4*)g_W2F)[j] = cast8(W2, j);
        } else if (i < PREP_S3) {
            int j = i - PREP_S2;
            uint4 r = make_uint4(0, 0, 0, 0);
            if (j < ASP_VALID8) r = cast8(aspects, j);
            ((uint4*)g_ASF)[j] = r;
        } else {
            int j = i - PREP_S3;
            int row = j / GITEMS_PER_ROW, c8 = j % GITEMS_PER_ROW;
            uint4 r = make_uint4(0, 0, 0, 0);
            if (c8 < GVALID_PER_ROW) {
                int src = idx[row];
                src = src < 0 ? 0 : (src >= NBRANDS ? NBRANDS - 1 : src);
                const float4* s = (const float4*)(emb + (size_t)src * NASPECT + c8 * 8);
                float4 a = s[0], b = s[1];
                r = make_uint4(pack_f16(__float2half_rn(a.x), __float2half_rn(a.y)),
                               pack_f16(__float2half_rn(a.z), __float2half_rn(a.w)),
                               pack_f16(__float2half_rn(b.x), __float2half_rn(b.y)),
                               pack_f16(__float2half_rn(b.z), __float2half_rn(b.w)));
            }
            ((uint4*)g_Gf)[j] = r;
        }
    }
}

// ---------------------------------------------------------------------------
// h_finalize: g_Hf = fp16(lrelu(Hp0 + Hp1 + b1))   (float4 vectorized)
// ---------------------------------------------------------------------------
__global__ void __launch_bounds__(256)
h_finalize(const float* __restrict__ b1)
{
    const int NT = gridDim.x * 256;
    const int N4 = BATCH * FCIN / 4;
    for (int i = blockIdx.x * 256 + threadIdx.x; i < N4; i += NT) {
        float4 a = ((const float4*)g_Hp)[i];
        float4 b = ((const float4*)g_Hp)[i + N4];
        float4 bb = ((const float4*)b1)[i & (FCIN / 4 - 1)];
        float v0 = a.x + b.x + bb.x;
        float v1 = a.y + b.y + bb.y;
        float v2 = a.z + b.z + bb.z;
        float v3 = a.w + b.w + bb.w;
        v0 = v0 > 0.f ? v0 : 0.01f * v0;
        v1 = v1 > 0.f ? v1 : 0.01f * v1;
        v2 = v2 > 0.f ? v2 : 0.01f * v2;
        v3 = v3 > 0.f ? v3 : 0.01f * v3;
        ((uint2*)g_Hf)[i] = make_uint2(
            pack_f16(__float2half_rn(v0), __float2half_rn(v1)),
            pack_f16(__float2half_rn(v2), __float2half_rn(v3)));
    }
}

// ---------------------------------------------------------------------------
// final_dot: out[b] = (1/NASPECT) * sum_e (ΣFp + b2)·(ΣVp)
// ---------------------------------------------------------------------------
__global__ void __launch_bounds__(256)
final_dot(const float* __restrict__ b2, float* __restrict__ out)
{
    const int b = blockIdx.x;
    const int j = threadIdx.x;             // EMBED/4 = 256
    const size_t off = (size_t)b * EMBED / 4;
    const int P = BATCH * EMBED / 4;

    float4 f = ((const float4*)g_Fp)[off + j];
    float4 t;
    t = ((const float4*)g_Fp)[off + j + P];     f.x += t.x; f.y += t.y; f.z += t.z; f.w += t.w;
    t = ((const float4*)g_Fp)[off + j + 2 * P]; f.x += t.x; f.y += t.y; f.z += t.z; f.w += t.w;
    t = ((const float4*)g_Fp)[off + j + 3 * P]; f.x += t.x; f.y += t.y; f.z += t.z; f.w += t.w;
    t = ((const float4*)b2)[j];                 f.x += t.x; f.y += t.y; f.z += t.z; f.w += t.w;

    float4 v = ((const float4*)g_Vp)[off + j];
    t = ((const float4*)g_Vp)[off + j + P];     v.x += t.x; v.y += t.y; v.z += t.z; v.w += t.w;

    float s = f.x * v.x + f.y * v.y + f.z * v.z + f.w * v.w;
    #pragma unroll
    for (int o = 16; o > 0; o >>= 1)
        s += __shfl_xor_sync(0xFFFFFFFFu, s, o);
    __shared__ float red[8];
    if ((threadIdx.x & 31) == 0) red[threadIdx.x >> 5] = s;
    __syncthreads();
    if (threadIdx.x < 8) {
        s = red[threadIdx.x];
        #pragma unroll
        for (int o = 4; o > 0; o >>= 1)
            s += __shfl_xor_sync(0xFFu, s, o);
        if (threadIdx.x == 0) out[b] = s * (1.0f / (float)NASPECT);
    }
}

// ---------------------------------------------------------------------------
#define SM_G1 (2 * (128 * (64 + 8) * 2 + 64 * (128 + 8) * 2))   // 71680
#define SM_G2 (2 * (64 * (64 + 8) * 2 + 64 * (64 + 8) * 2))     // 36864

extern "C" void kernel_launch(void* const* d_in, const int* in_sizes, int n_in,
                              void* d_out, int out_size)
{
    const float* image     = (const float*)d_in[0];
    const int*   brand     = (const int*)d_in[1];
    const float* W1        = (const float*)d_in[2];
    const float* b1        = (const float*)d_in[3];
    const float* W2        = (const float*)d_in[4];
    const float* b2        = (const float*)d_in[5];
    const float* brand_emb = (const float*)d_in[6];
    const float* aspects   = (const float*)d_in[7];
    float*       out       = (float*)d_out;

    static bool init = false;
    if (!init) {
        cudaFuncSetAttribute((const void*)gemm1_split,
                             cudaFuncAttributeMaxDynamicSharedMemorySize, SM_G1);
        cudaFuncSetAttribute((const void*)gemm23_split,
                             cudaFuncAttributeMaxDynamicSharedMemorySize, SM_G2);
        init = true;
    }

    // All operand conversions, one launch
    prep_all<<<4096, 256>>>(image, W1, W2, aspects, brand_emb, brand);

    // GEMM1 split-K2: Hp[z] = image_z @ W1_z   (256 CTAs)
    gemm1_split<<<dim3(FCIN / 128, BATCH / 128, 2), 256, SM_G1>>>();

    // Hf = fp16(lrelu(Hp0 + Hp1 + b1))
    h_finalize<<<2048, 256>>>(b1);

    // Fused GEMM2 split-K4 + GEMM3 split-K2  (768 CTAs)
    gemm23_split<<<dim3(EMBED / 64, BATCH / 64, 6), 256, SM_G2>>>();

    // out = mean reduce of (ΣFp + b2)·(ΣVp)
    final_dot<<<BATCH, 256>>>(b2, out);
}

// round 16
// speedup vs baseline: 2.0601x; 1.0149x over previous
#include <cuda_runtime.h>
#include <cuda_bf16.h>
#include <cuda_fp16.h>
#include <cstdint>

#define BATCH   512
#define FCIN    4096
#define EMBED   1024
#define NASPECT 2000
#define NASPAD  2048
#define NBRANDS 10000

// ---------------------------------------------------------------------------
// Scratch
// ---------------------------------------------------------------------------
__device__ __align__(256) __half g_imgF[BATCH * FCIN];
__device__ __align__(256) __half g_W1F[FCIN * FCIN];       // [K,N]
__device__ __align__(256) float  g_Hp[4 * BATCH * FCIN];   // GEMM1 partials (K/4 each)
__device__ __align__(256) __half g_Hf[BATCH * FCIN];       // lrelu out
__device__ __align__(256) __half g_W2F[FCIN * EMBED];      // [K,N]
__device__ __align__(256) __half g_Gf[BATCH * NASPAD];     // gathered, padded
__device__ __align__(256) __half g_ASF[NASPAD * EMBED];    // [Kpad,N], padded
__device__ __align__(256) float  g_Fp[8 * BATCH * EMBED];  // GEMM2 partials (K/8)
__device__ __align__(256) float  g_Vp[4 * BATCH * EMBED];  // GEMM3 partials (K/4)

// ---------------------------------------------------------------------------
// PTX helpers
// ---------------------------------------------------------------------------
__device__ __forceinline__ uint32_t smem_u32(const void* p) {
    uint32_t a;
    asm("{ .reg .u64 t; cvta.to.shared.u64 t, %1; cvt.u32.u64 %0, t; }"
        : "=r"(a) : "l"(p));
    return a;
}
__device__ __forceinline__ void ldsm4(uint32_t* r, uint32_t addr) {
    asm volatile("ldmatrix.sync.aligned.m8n8.x4.shared.b16 {%0,%1,%2,%3}, [%4];"
        : "=r"(r[0]), "=r"(r[1]), "=r"(r[2]), "=r"(r[3]) : "r"(addr));
}
__device__ __forceinline__ void ldsm2t(uint32_t* r, uint32_t addr) {
    asm volatile("ldmatrix.sync.aligned.m8n8.x2.trans.shared.b16 {%0,%1}, [%2];"
        : "=r"(r[0]), "=r"(r[1]) : "r"(addr));
}
__device__ __forceinline__ void mma_f16(float* d, const uint32_t* a, const uint32_t* b) {
    asm volatile("mma.sync.aligned.m16n8k16.row.col.f32.f16.f16.f32 "
        "{%0,%1,%2,%3}, {%4,%5,%6,%7}, {%8,%9}, {%0,%1,%2,%3};"
        : "+f"(d[0]), "+f"(d[1]), "+f"(d[2]), "+f"(d[3])
        : "r"(a[0]), "r"(a[1]), "r"(a[2]), "r"(a[3]), "r"(b[0]), "r"(b[1]));
}
__device__ __forceinline__ void cpa16(uint32_t d, const void* s) {
    asm volatile("cp.async.cg.shared.global [%0], [%1], 16;" :: "r"(d), "l"(s));
}
#define CPA_COMMIT() asm volatile("cp.async.commit_group;" ::: "memory")
#define CPA_WAIT(n)  asm volatile("cp.async.wait_group %0;" :: "n"(n) : "memory")

__device__ __forceinline__ uint32_t pack_f16(__half a, __half b) {
    return (uint32_t)*(uint16_t*)&a | ((uint32_t)*(uint16_t*)&b << 16);
}

// ---------------------------------------------------------------------------
// GEMM core macro (validated): 256 threads, double-buffered cp.async pipeline.
// ---------------------------------------------------------------------------
#define GEMM_CORE(BM, BN, BK, WM, WN, srcA, srcB, lda, ldb, NC, acc)           \
    constexpr int SA = (BK + 8) * 2;                                           \
    constexpr int SB = (BN + 8) * 2;                                           \
    constexpr int OFF_A = 0;                                                   \
    constexpr int OFF_B = BM * SA;                                             \
    constexpr int BUFB = BM * SA + BK * SB;                                    \
    constexpr int MI = WM / 16, NI = WN / 8;                                   \
    constexpr int KS = BK / 16;                                                \
    constexpr int AK8 = BK / 8;                                                \
    constexpr int BN8 = BN / 8;                                                \
    extern __shared__ __align__(128) char smem[];                              \
    const uint32_t sbm = smem_u32(smem);                                       \
    const int tid = threadIdx.x, wid = tid >> 5, lane = tid & 31;              \
    const int wm = wid % (BM / WM), wn = wid / (BM / WM);                      \
    _Pragma("unroll")                                                          \
    for (int i = 0; i < MI; i++)                                               \
        _Pragma("unroll")                                                      \
        for (int j = 0; j < NI; j++)                                           \
            _Pragma("unroll")                                                  \
            for (int q = 0; q < 4; q++) acc[i][j][q] = 0.f;                    \
    const uint32_t aBase = (uint32_t)((wm * WM + (lane & 15)) * SA + (lane >> 4) * 16); \
    const uint32_t bBase = (uint32_t)((lane & 15) * SB + (wn * WN) * 2);       \
    auto prefetch = [&](int chunk, int p) {                                    \
        const uint32_t tb = sbm + p * BUFB;                                    \
        const int k0 = chunk * BK;                                             \
        _Pragma("unroll")                                                      \
        for (int i = tid; i < BM * AK8; i += 256) {                            \
            int r = i / AK8, c = i % AK8;                                      \
            cpa16(tb + OFF_A + (uint32_t)(r * SA + c * 16),                    \
                  srcA + (size_t)r * lda + k0 + c * 8);                        \
        }                                                                      \
        _Pragma("unroll")                                                      \
        for (int i = tid; i < BK * BN8; i += 256) {                            \
            int r = i / BN8, c = i % BN8;                                      \
            cpa16(tb + OFF_B + (uint32_t)(r * SB + c * 16),                    \
                  srcB + (size_t)(k0 + r) * ldb + c * 8);                      \
        }                                                                      \
        CPA_COMMIT();                                                          \
    };                                                                         \
    prefetch(0, 0);                                                            \
    for (int c = 0; c < NC; c++) {                                             \
        const int p = c & 1;                                                   \
        if (c + 1 < NC) { prefetch(c + 1, (c + 1) & 1); CPA_WAIT(1); }         \
        else            { CPA_WAIT(0); }                                       \
        __syncthreads();                                                       \
        const uint32_t tb = sbm + p * BUFB;                                    \
        _Pragma("unroll")                                                      \
        for (int ks = 0; ks < KS; ks++) {                                      \
            uint32_t aF[MI][4], bF[NI][2];                                     \
            _Pragma("unroll")                                                  \
            for (int mi = 0; mi < MI; mi++)                                    \
                ldsm4(aF[mi], tb + OFF_A + aBase + (uint32_t)(mi * 16 * SA + ks * 32)); \
            _Pragma("unroll")                                                  \
            for (int ni = 0; ni < NI; ni++)                                    \
                ldsm2t(bF[ni], tb + OFF_B + bBase + (uint32_t)(ks * 16 * SB + ni * 16)); \
            _Pragma("unroll")                                                  \
            for (int mi = 0; mi < MI; mi++)                                    \
                _Pragma("unroll")                                              \
                for (int ni = 0; ni < NI; ni++)                                \
                    mma_f16(acc[mi][ni], aF[mi], bF[ni]);                      \
        }                                                                      \
        __syncthreads();                                                       \
    }

// ---------------------------------------------------------------------------
// GEMM1 split-K4: partial z = image[:, z*1024:...] @ W1[z*1024:..., :]
// 128x128 tile, grid (32, 4, 4) = 512 CTAs. Raw fp32 partial to g_Hp[z].
// ---------------------------------------------------------------------------
__global__ void __launch_bounds__(256)
gemm1_split()
{
    const int z = blockIdx.z;
    const int rowbase = blockIdx.y * 128, colbase = blockIdx.x * 128;
    const int kb = z * 1024;
    const __half* srcA = g_imgF + (size_t)rowbase * FCIN + kb;
    const __half* srcB = g_W1F + (size_t)kb * FCIN + colbase;
    float* Cout = g_Hp + (size_t)z * BATCH * FCIN;

    float acc[4][4][4];
    GEMM_CORE(128, 128, 64, 64, 32, srcA, srcB, FCIN, FCIN, 16, acc)

    const int r0 = rowbase + wm * 64 + (lane >> 2);
    const int c0 = colbase + wn * 32 + (lane & 3) * 2;
    #pragma unroll
    for (int mi = 0; mi < 4; mi++)
        #pragma unroll
        for (int ni = 0; ni < 4; ni++)
            #pragma unroll
            for (int h = 0; h < 2; h++) {
                const int rr = r0 + mi * 16 + h * 8;
                *(float2*)(Cout + (size_t)rr * FCIN + c0 + ni * 8) =
                    make_float2(acc[mi][ni][2 * h], acc[mi][ni][2 * h + 1]);
            }
}

// ---------------------------------------------------------------------------
// Fused GEMM2 (split-K8) + GEMM3 (split-K4): 64x128 tiles, warp tile 32x32,
// grid (8, 8, 12) = 768 CTAs. K_len = 512 uniform (NC=8).
// z in [0,8): F partial z; z in [8,12): V partial z-8.
// ---------------------------------------------------------------------------
__global__ void __launch_bounds__(256)
gemm23_split()
{
    const int z = blockIdx.z;
    const int rowbase = blockIdx.y * 64, colbase = blockIdx.x * 128;
    const __half* srcA;
    const __half* srcB;
    float* Cout;
    int lda;
    if (z < 8) {
        lda  = FCIN;
        srcA = g_Hf + (size_t)rowbase * FCIN + z * 512;
        srcB = g_W2F + (size_t)z * 512 * EMBED + colbase;
        Cout = g_Fp + (size_t)z * BATCH * EMBED;
    } else {
        const int zz = z - 8;
        lda  = NASPAD;
        srcA = g_Gf + (size_t)rowbase * NASPAD + zz * 512;
        srcB = g_ASF + (size_t)zz * 512 * EMBED + colbase;
        Cout = g_Vp + (size_t)zz * BATCH * EMBED;
    }

    float acc[2][4][4];
    GEMM_CORE(64, 128, 64, 32, 32, srcA, srcB, lda, EMBED, 8, acc)

    const int r0 = rowbase + wm * 32 + (lane >> 2);
    const int c0 = colbase + wn * 32 + (lane & 3) * 2;
    #pragma unroll
    for (int mi = 0; mi < 2; mi++)
        #pragma unroll
        for (int ni = 0; ni < 4; ni++)
            #pragma unroll
            for (int h = 0; h < 2; h++) {
                const int rr = r0 + mi * 16 + h * 8;
                *(float2*)(Cout + (size_t)rr * EMBED + c0 + ni * 8) =
                    make_float2(acc[mi][ni][2 * h], acc[mi][ni][2 * h + 1]);
            }
}

// ---------------------------------------------------------------------------
// prep_all: all operand conversions in one launch (validated R14)
// ---------------------------------------------------------------------------
#define PREP_S0 (BATCH * FCIN / 8)
#define PREP_S1 (PREP_S0 + FCIN * FCIN / 8)
#define PREP_S2 (PREP_S1 + FCIN * EMBED / 8)
#define PREP_S3 (PREP_S2 + NASPAD * EMBED / 8)
#define PREP_S4 (PREP_S3 + BATCH * NASPAD / 8)
#define ASP_VALID8 (NASPECT * EMBED / 8)
#define GITEMS_PER_ROW (NASPAD / 8)
#define GVALID_PER_ROW (NASPECT / 8)

__device__ __forceinline__ uint4 cast8(const float* __restrict__ src, int i8)
{
    float4 a = ((const float4*)src)[2 * i8];
    float4 b = ((const float4*)src)[2 * i8 + 1];
    return make_uint4(pack_f16(__float2half_rn(a.x), __float2half_rn(a.y)),
                      pack_f16(__float2half_rn(a.z), __float2half_rn(a.w)),
                      pack_f16(__float2half_rn(b.x), __float2half_rn(b.y)),
                      pack_f16(__float2half_rn(b.z), __float2half_rn(b.w)));
}

__global__ void __launch_bounds__(256)
prep_all(const float* __restrict__ image, const float* __restrict__ W1,
         const float* __restrict__ W2, const float* __restrict__ aspects,
         const float* __restrict__ emb, const int* __restrict__ idx)
{
    const int NT = gridDim.x * 256;
    for (int i = blockIdx.x * 256 + threadIdx.x; i < PREP_S4; i += NT) {
        if (i < PREP_S0) {
            ((uint4*)g_imgF)[i] = cast8(image, i);
        } else if (i < PREP_S1) {
            int j = i - PREP_S0;
            ((uint4*)g_W1F)[j] = cast8(W1, j);
        } else if (i < PREP_S2) {
            int j = i - PREP_S1;
            ((uint4*)g_W2F)[j] = cast8(W2, j);
        } else if (i < PREP_S3) {
            int j = i - PREP_S2;
            uint4 r = make_uint4(0, 0, 0, 0);
            if (j < ASP_VALID8) r = cast8(aspects, j);
            ((uint4*)g_ASF)[j] = r;
        } else {
            int j = i - PREP_S3;
            int row = j / GITEMS_PER_ROW, c8 = j % GITEMS_PER_ROW;
            uint4 r = make_uint4(0, 0, 0, 0);
            if (c8 < GVALID_PER_ROW) {
                int src = idx[row];
                src = src < 0 ? 0 : (src >= NBRANDS ? NBRANDS - 1 : src);
                const float4* s = (const float4*)(emb + (size_t)src * NASPECT + c8 * 8);
                float4 a = s[0], b = s[1];
                r = make_uint4(pack_f16(__float2half_rn(a.x), __float2half_rn(a.y)),
                               pack_f16(__float2half_rn(a.z), __float2half_rn(a.w)),
                               pack_f16(__float2half_rn(b.x), __float2half_rn(b.y)),
                               pack_f16(__float2half_rn(b.z), __float2half_rn(b.w)));
            }
            ((uint4*)g_Gf)[j] = r;
        }
    }
}

// ---------------------------------------------------------------------------
// h_finalize: g_Hf = fp16(lrelu(Hp0+Hp1+Hp2+Hp3 + b1))
// ---------------------------------------------------------------------------
__global__ void __launch_bounds__(256)
h_finalize(const float* __restrict__ b1)
{
    const int NT = gridDim.x * 256;
    const int N4 = BATCH * FCIN / 4;
    for (int i = blockIdx.x * 256 + threadIdx.x; i < N4; i += NT) {
        float4 a = ((const float4*)g_Hp)[i];
        float4 t;
        t = ((const float4*)g_Hp)[i + N4];     a.x += t.x; a.y += t.y; a.z += t.z; a.w += t.w;
        t = ((const float4*)g_Hp)[i + 2 * N4]; a.x += t.x; a.y += t.y; a.z += t.z; a.w += t.w;
        t = ((const float4*)g_Hp)[i + 3 * N4]; a.x += t.x; a.y += t.y; a.z += t.z; a.w += t.w;
        float4 bb = ((const float4*)b1)[i & (FCIN / 4 - 1)];
        float v0 = a.x + bb.x, v1 = a.y + bb.y, v2 = a.z + bb.z, v3 = a.w + bb.w;
        v0 = v0 > 0.f ? v0 : 0.01f * v0;
        v1 = v1 > 0.f ? v1 : 0.01f * v1;
        v2 = v2 > 0.f ? v2 : 0.01f * v2;
        v3 = v3 > 0.f ? v3 : 0.01f * v3;
        ((uint2*)g_Hf)[i] = make_uint2(
            pack_f16(__float2half_rn(v0), __float2half_rn(v1)),
            pack_f16(__float2half_rn(v2), __float2half_rn(v3)));
    }
}

// ---------------------------------------------------------------------------
// final_dot: out[b] = (1/NASPECT) * sum_e (ΣFp + b2)·(ΣVp)
// ---------------------------------------------------------------------------
__global__ void __launch_bounds__(256)
final_dot(const float* __restrict__ b2, float* __restrict__ out)
{
    const int b = blockIdx.x;
    const int j = threadIdx.x;             // EMBED/4 = 256
    const size_t off = (size_t)b * EMBED / 4;
    const int P = BATCH * EMBED / 4;

    float4 f = ((const float4*)g_Fp)[off + j];
    float4 t;
    #pragma unroll
    for (int zz = 1; zz < 8; zz++) {
        t = ((const float4*)g_Fp)[off + j + (size_t)zz * P];
        f.x += t.x; f.y += t.y; f.z += t.z; f.w += t.w;
    }
    t = ((const float4*)b2)[j];
    f.x += t.x; f.y += t.y; f.z += t.z; f.w += t.w;

    float4 v = ((const float4*)g_Vp)[off + j];
    #pragma unroll
    for (int zz = 1; zz < 4; zz++) {
        t = ((const float4*)g_Vp)[off + j + (size_t)zz * P];
        v.x += t.x; v.y += t.y; v.z += t.z; v.w += t.w;
    }

    float s = f.x * v.x + f.y * v.y + f.z * v.z + f.w * v.w;
    #pragma unroll
    for (int o = 16; o > 0; o >>= 1)
        s += __shfl_xor_sync(0xFFFFFFFFu, s, o);
    __shared__ float red[8];
    if ((threadIdx.x & 31) == 0) red[threadIdx.x >> 5] = s;
    __syncthreads();
    if (threadIdx.x < 8) {
        s = red[threadIdx.x];
        #pragma unroll
        for (int o = 4; o > 0; o >>= 1)
            s += __shfl_xor_sync(0xFFu, s, o);
        if (threadIdx.x == 0) out[b] = s * (1.0f / (float)NASPECT);
    }
}

// ---------------------------------------------------------------------------
#define SM_G1  (2 * (128 * (64 + 8) * 2 + 64 * (128 + 8) * 2))  // 71680
#define SM_G23 (2 * (64 * (64 + 8) * 2 + 64 * (128 + 8) * 2))   // 53248

extern "C" void kernel_launch(void* const* d_in, const int* in_sizes, int n_in,
                              void* d_out, int out_size)
{
    const float* image     = (const float*)d_in[0];
    const int*   brand     = (const int*)d_in[1];
    const float* W1        = (const float*)d_in[2];
    const float* b1        = (const float*)d_in[3];
    const float* W2        = (const float*)d_in[4];
    const float* b2        = (const float*)d_in[5];
    const float* brand_emb = (const float*)d_in[6];
    const float* aspects   = (const float*)d_in[7];
    float*       out       = (float*)d_out;

    static bool init = false;
    if (!init) {
        cudaFuncSetAttribute((const void*)gemm1_split,
                             cudaFuncAttributeMaxDynamicSharedMemorySize, SM_G1);
        cudaFuncSetAttribute((const void*)gemm23_split,
                             cudaFuncAttributeMaxDynamicSharedMemorySize, SM_G23);
        init = true;
    }

    // All operand conversions, one launch
    prep_all<<<4096, 256>>>(image, W1, W2, aspects, brand_emb, brand);

    // GEMM1 split-K4: Hp[z] = image_z @ W1_z   (512 CTAs)
    gemm1_split<<<dim3(FCIN / 128, BATCH / 128, 4), 256, SM_G1>>>();

    // Hf = fp16(lrelu(sum Hp + b1))
    h_finalize<<<2048, 256>>>(b1);

    // Fused GEMM2 split-K8 + GEMM3 split-K4  (768 CTAs, 64x128 tiles)
    gemm23_split<<<dim3(EMBED / 128, BATCH / 64, 12), 256, SM_G23>>>();

    // out = mean reduce of (ΣFp + b2)·(ΣVp)
    final_dot<<<BATCH, 256>>>(b2, out);
}

// round 17
// speedup vs baseline: 2.1250x; 1.0315x over previous
#include <cuda_runtime.h>
#include <cuda_bf16.h>
#include <cuda_fp16.h>
#include <cstdint>

#define BATCH   512
#define FCIN    4096
#define EMBED   1024
#define NASPECT 2000
#define NASPAD  2048
#define NBRANDS 10000

// ---------------------------------------------------------------------------
// Scratch
// ---------------------------------------------------------------------------
__device__ __align__(256) __half g_imgF[BATCH * FCIN];
__device__ __align__(256) __half g_W1F[FCIN * FCIN];       // [K,N]
__device__ __align__(256) float  g_Hp[4 * BATCH * FCIN];   // GEMM1 partials
__device__ __align__(256) __half g_Hf[BATCH * FCIN];       // lrelu out
__device__ __align__(256) __half g_W2F[FCIN * EMBED];      // [K,N]
__device__ __align__(256) __half g_Gf[BATCH * NASPAD];     // gathered, padded
__device__ __align__(256) __half g_ASF[NASPAD * EMBED];    // [Kpad,N], padded
__device__ __align__(256) float  g_Fp[8 * BATCH * EMBED];  // GEMM2 partials
__device__ __align__(256) float  g_Vp[4 * BATCH * EMBED];  // GEMM3 partials

// ---------------------------------------------------------------------------
// PTX helpers
// ---------------------------------------------------------------------------
__device__ __forceinline__ uint32_t smem_u32(const void* p) {
    uint32_t a;
    asm("{ .reg .u64 t; cvta.to.shared.u64 t, %1; cvt.u32.u64 %0, t; }"
        : "=r"(a) : "l"(p));
    return a;
}
__device__ __forceinline__ void ldsm4(uint32_t* r, uint32_t addr) {
    asm volatile("ldmatrix.sync.aligned.m8n8.x4.shared.b16 {%0,%1,%2,%3}, [%4];"
        : "=r"(r[0]), "=r"(r[1]), "=r"(r[2]), "=r"(r[3]) : "r"(addr));
}
// x4 trans: m0,m1 from lanes 0-15 (col-block base, k rows 0-7 / 8-15),
//           m2,m3 from lanes 16-31 (col-block base+8). One instr = b-frags
//           for TWO adjacent 8-col n-blocks.
__device__ __forceinline__ void ldsm4t(uint32_t* r, uint32_t addr) {
    asm volatile("ldmatrix.sync.aligned.m8n8.x4.trans.shared.b16 {%0,%1,%2,%3}, [%4];"
        : "=r"(r[0]), "=r"(r[1]), "=r"(r[2]), "=r"(r[3]) : "r"(addr));
}
__device__ __forceinline__ void mma_f16(float* d, const uint32_t* a, const uint32_t* b) {
    asm volatile("mma.sync.aligned.m16n8k16.row.col.f32.f16.f16.f32 "
        "{%0,%1,%2,%3}, {%4,%5,%6,%7}, {%8,%9}, {%0,%1,%2,%3};"
        : "+f"(d[0]), "+f"(d[1]), "+f"(d[2]), "+f"(d[3])
        : "r"(a[0]), "r"(a[1]), "r"(a[2]), "r"(a[3]), "r"(b[0]), "r"(b[1]));
}
__device__ __forceinline__ void cpa16(uint32_t d, const void* s) {
    asm volatile("cp.async.cg.shared.global [%0], [%1], 16;" :: "r"(d), "l"(s));
}
#define CPA_COMMIT() asm volatile("cp.async.commit_group;" ::: "memory")
#define CPA_WAIT(n)  asm volatile("cp.async.wait_group %0;" :: "n"(n) : "memory")

__device__ __forceinline__ uint32_t pack_f16(__half a, __half b) {
    return (uint32_t)*(uint16_t*)&a | ((uint32_t)*(uint16_t*)&b << 16);
}

// ---------------------------------------------------------------------------
// GEMM core macro: 256 threads, double-buffered cp.async pipeline.
// B fragments fetched pairwise with ldmatrix.x4.trans (NI must be even).
// ---------------------------------------------------------------------------
#define GEMM_CORE(BM, BN, BK, WM, WN, srcA, srcB, lda, ldb, NC, acc)           \
    constexpr int SA = (BK + 8) * 2;                                           \
    constexpr int SB = (BN + 8) * 2;                                           \
    constexpr int OFF_A = 0;                                                   \
    constexpr int OFF_B = BM * SA;                                             \
    constexpr int BUFB = BM * SA + BK * SB;                                    \
    constexpr int MI = WM / 16, NI = WN / 8;                                   \
    constexpr int KS = BK / 16;                                                \
    constexpr int AK8 = BK / 8;                                                \
    constexpr int BN8 = BN / 8;                                                \
    static_assert((NI & 1) == 0, "NI must be even for x4.trans");              \
    extern __shared__ __align__(128) char smem[];                              \
    const uint32_t sbm = smem_u32(smem);                                       \
    const int tid = threadIdx.x, wid = tid >> 5, lane = tid & 31;              \
    const int wm = wid % (BM / WM), wn = wid / (BM / WM);                      \
    _Pragma("unroll")                                                          \
    for (int i = 0; i < MI; i++)                                               \
        _Pragma("unroll")                                                      \
        for (int j = 0; j < NI; j++)                                           \
            _Pragma("unroll")                                                  \
            for (int q = 0; q < 4; q++) acc[i][j][q] = 0.f;                    \
    const uint32_t aBase = (uint32_t)((wm * WM + (lane & 15)) * SA + (lane >> 4) * 16); \
    const uint32_t bBase4 = (uint32_t)((lane & 15) * SB +                      \
                                       (wn * WN + ((lane >> 4) << 3)) * 2);    \
    auto prefetch = [&](int chunk, int p) {                                    \
        const uint32_t tb = sbm + p * BUFB;                                    \
        const int k0 = chunk * BK;                                             \
        _Pragma("unroll")                                                      \
        for (int i = tid; i < BM * AK8; i += 256) {                            \
            int r = i / AK8, c = i % AK8;                                      \
            cpa16(tb + OFF_A + (uint32_t)(r * SA + c * 16),                    \
                  srcA + (size_t)r * lda + k0 + c * 8);                        \
        }                                                                      \
        _Pragma("unroll")                                                      \
        for (int i = tid; i < BK * BN8; i += 256) {                            \
            int r = i / BN8, c = i % BN8;                                      \
            cpa16(tb + OFF_B + (uint32_t)(r * SB + c * 16),                    \
                  srcB + (size_t)(k0 + r) * ldb + c * 8);                      \
        }                                                                      \
        CPA_COMMIT();                                                          \
    };                                                                         \
    prefetch(0, 0);                                                            \
    for (int c = 0; c < NC; c++) {                                             \
        const int p = c & 1;                                                   \
        if (c + 1 < NC) { prefetch(c + 1, (c + 1) & 1); CPA_WAIT(1); }         \
        else            { CPA_WAIT(0); }                                       \
        __syncthreads();                                                       \
        const uint32_t tb = sbm + p * BUFB;                                    \
        _Pragma("unroll")                                                      \
        for (int ks = 0; ks < KS; ks++) {                                      \
            uint32_t aF[MI][4], bF[NI][2];                                     \
            _Pragma("unroll")                                                  \
            for (int mi = 0; mi < MI; mi++)                                    \
                ldsm4(aF[mi], tb + OFF_A + aBase + (uint32_t)(mi * 16 * SA + ks * 32)); \
            _Pragma("unroll")                                                  \
            for (int ni = 0; ni < NI; ni += 2) {                               \
                uint32_t bq[4];                                                \
                ldsm4t(bq, tb + OFF_B + bBase4 +                               \
                           (uint32_t)(ks * 16 * SB + ni * 16));                \
                bF[ni][0] = bq[0]; bF[ni][1] = bq[1];                          \
                bF[ni + 1][0] = bq[2]; bF[ni + 1][1] = bq[3];                  \
            }                                                                  \
            _Pragma("unroll")                                                  \
            for (int mi = 0; mi < MI; mi++)                                    \
                _Pragma("unroll")                                              \
                for (int ni = 0; ni < NI; ni++)                                \
                    mma_f16(acc[mi][ni], aF[mi], bF[ni]);                      \
        }                                                                      \
        __syncthreads();                                                       \
    }

// ---------------------------------------------------------------------------
// GEMM1 split-K4: 128x128 tile, grid (32, 4, 4) = 512 CTAs. fp32 partials.
// ---------------------------------------------------------------------------
__global__ void __launch_bounds__(256)
gemm1_split()
{
    const int z = blockIdx.z;
    const int rowbase = blockIdx.y * 128, colbase = blockIdx.x * 128;
    const int kb = z * 1024;
    const __half* srcA = g_imgF + (size_t)rowbase * FCIN + kb;
    const __half* srcB = g_W1F + (size_t)kb * FCIN + colbase;
    float* Cout = g_Hp + (size_t)z * BATCH * FCIN;

    float acc[4][4][4];
    GEMM_CORE(128, 128, 64, 64, 32, srcA, srcB, FCIN, FCIN, 16, acc)

    const int r0 = rowbase + wm * 64 + (lane >> 2);
    const int c0 = colbase + wn * 32 + (lane & 3) * 2;
    #pragma unroll
    for (int mi = 0; mi < 4; mi++)
        #pragma unroll
        for (int ni = 0; ni < 4; ni++)
            #pragma unroll
            for (int h = 0; h < 2; h++) {
                const int rr = r0 + mi * 16 + h * 8;
                *(float2*)(Cout + (size_t)rr * FCIN + c0 + ni * 8) =
                    make_float2(acc[mi][ni][2 * h], acc[mi][ni][2 * h + 1]);
            }
}

// ---------------------------------------------------------------------------
// Fused GEMM2 (split-K8) + GEMM3 (split-K4): 64x128 tiles, warp 32x32,
// grid (8, 8, 12) = 768 CTAs, K_len = 512 (NC=8).
// ---------------------------------------------------------------------------
__global__ void __launch_bounds__(256)
gemm23_split()
{
    const int z = blockIdx.z;
    const int rowbase = blockIdx.y * 64, colbase = blockIdx.x * 128;
    const __half* srcA;
    const __half* srcB;
    float* Cout;
    int lda;
    if (z < 8) {
        lda  = FCIN;
        srcA = g_Hf + (size_t)rowbase * FCIN + z * 512;
        srcB = g_W2F + (size_t)z * 512 * EMBED + colbase;
        Cout = g_Fp + (size_t)z * BATCH * EMBED;
    } else {
        const int zz = z - 8;
        lda  = NASPAD;
        srcA = g_Gf + (size_t)rowbase * NASPAD + zz * 512;
        srcB = g_ASF + (size_t)zz * 512 * EMBED + colbase;
        Cout = g_Vp + (size_t)zz * BATCH * EMBED;
    }

    float acc[2][4][4];
    GEMM_CORE(64, 128, 64, 32, 32, srcA, srcB, lda, EMBED, 8, acc)

    const int r0 = rowbase + wm * 32 + (lane >> 2);
    const int c0 = colbase + wn * 32 + (lane & 3) * 2;
    #pragma unroll
    for (int mi = 0; mi < 2; mi++)
        #pragma unroll
        for (int ni = 0; ni < 4; ni++)
            #pragma unroll
            for (int h = 0; h < 2; h++) {
                const int rr = r0 + mi * 16 + h * 8;
                *(float2*)(Cout + (size_t)rr * EMBED + c0 + ni * 8) =
                    make_float2(acc[mi][ni][2 * h], acc[mi][ni][2 * h + 1]);
            }
}

// ---------------------------------------------------------------------------
// prep_all: all operand conversions in one launch (validated R14)
// ---------------------------------------------------------------------------
#define PREP_S0 (BATCH * FCIN / 8)
#define PREP_S1 (PREP_S0 + FCIN * FCIN / 8)
#define PREP_S2 (PREP_S1 + FCIN * EMBED / 8)
#define PREP_S3 (PREP_S2 + NASPAD * EMBED / 8)
#define PREP_S4 (PREP_S3 + BATCH * NASPAD / 8)
#define ASP_VALID8 (NASPECT * EMBED / 8)
#define GITEMS_PER_ROW (NASPAD / 8)
#define GVALID_PER_ROW (NASPECT / 8)

__device__ __forceinline__ uint4 cast8(const float* __restrict__ src, int i8)
{
    float4 a = ((const float4*)src)[2 * i8];
    float4 b = ((const float4*)src)[2 * i8 + 1];
    return make_uint4(pack_f16(__float2half_rn(a.x), __float2half_rn(a.y)),
                      pack_f16(__float2half_rn(a.z), __float2half_rn(a.w)),
                      pack_f16(__float2half_rn(b.x), __float2half_rn(b.y)),
                      pack_f16(__float2half_rn(b.z), __float2half_rn(b.w)));
}

__global__ void __launch_bounds__(256)
prep_all(const float* __restrict__ image, const float* __restrict__ W1,
         const float* __restrict__ W2, const float* __restrict__ aspects,
         const float* __restrict__ emb, const int* __restrict__ idx)
{
    const int NT = gridDim.x * 256;
    for (int i = blockIdx.x * 256 + threadIdx.x; i < PREP_S4; i += NT) {
        if (i < PREP_S0) {
            ((uint4*)g_imgF)[i] = cast8(image, i);
        } else if (i < PREP_S1) {
            int j = i - PREP_S0;
            ((uint4*)g_W1F)[j] = cast8(W1, j);
        } else if (i < PREP_S2) {
            int j = i - PREP_S1;
            ((uint4*)g_W2F)[j] = cast8(W2, j);
        } else if (i < PREP_S3) {
            int j = i - PREP_S2;
            uint4 r = make_uint4(0, 0, 0, 0);
            if (j < ASP_VALID8) r = cast8(aspects, j);
            ((uint4*)g_ASF)[j] = r;
        } else {
            int j = i - PREP_S3;
            int row = j / GITEMS_PER_ROW, c8 = j % GITEMS_PER_ROW;
            uint4 r = make_uint4(0, 0, 0, 0);
            if (c8 < GVALID_PER_ROW) {
                int src = idx[row];
                src = src < 0 ? 0 : (src >= NBRANDS ? NBRANDS - 1 : src);
                const float4* s = (const float4*)(emb + (size_t)src * NASPECT + c8 * 8);
                float4 a = s[0], b = s[1];
                r = make_uint4(pack_f16(__float2half_rn(a.x), __float2half_rn(a.y)),
                               pack_f16(__float2half_rn(a.z), __float2half_rn(a.w)),
                               pack_f16(__float2half_rn(b.x), __float2half_rn(b.y)),
                               pack_f16(__float2half_rn(b.z), __float2half_rn(b.w)));
            }
            ((uint4*)g_Gf)[j] = r;
        }
    }
}

// ---------------------------------------------------------------------------
// h_finalize: g_Hf = fp16(lrelu(Hp0+Hp1+Hp2+Hp3 + b1))
// ---------------------------------------------------------------------------
__global__ void __launch_bounds__(256)
h_finalize(const float* __restrict__ b1)
{
    const int NT = gridDim.x * 256;
    const int N4 = BATCH * FCIN / 4;
    for (int i = blockIdx.x * 256 + threadIdx.x; i < N4; i += NT) {
        float4 a = ((const float4*)g_Hp)[i];
        float4 t;
        t = ((const float4*)g_Hp)[i + N4];     a.x += t.x; a.y += t.y; a.z += t.z; a.w += t.w;
        t = ((const float4*)g_Hp)[i + 2 * N4]; a.x += t.x; a.y += t.y; a.z += t.z; a.w += t.w;
        t = ((const float4*)g_Hp)[i + 3 * N4]; a.x += t.x; a.y += t.y; a.z += t.z; a.w += t.w;
        float4 bb = ((const float4*)b1)[i & (FCIN / 4 - 1)];
        float v0 = a.x + bb.x, v1 = a.y + bb.y, v2 = a.z + bb.z, v3 = a.w + bb.w;
        v0 = v0 > 0.f ? v0 : 0.01f * v0;
        v1 = v1 > 0.f ? v1 : 0.01f * v1;
        v2 = v2 > 0.f ? v2 : 0.01f * v2;
        v3 = v3 > 0.f ? v3 : 0.01f * v3;
        ((uint2*)g_Hf)[i] = make_uint2(
            pack_f16(__float2half_rn(v0), __float2half_rn(v1)),
            pack_f16(__float2half_rn(v2), __float2half_rn(v3)));
    }
}

// ---------------------------------------------------------------------------
// final_dot: out[b] = (1/NASPECT) * sum_e (ΣFp + b2)·(ΣVp)
// ---------------------------------------------------------------------------
__global__ void __launch_bounds__(256)
final_dot(const float* __restrict__ b2, float* __restrict__ out)
{
    const int b = blockIdx.x;
    const int j = threadIdx.x;             // EMBED/4 = 256
    const size_t off = (size_t)b * EMBED / 4;
    const int P = BATCH * EMBED / 4;

    float4 f = ((const float4*)g_Fp)[off + j];
    float4 t;
    #pragma unroll
    for (int zz = 1; zz < 8; zz++) {
        t = ((const float4*)g_Fp)[off + j + (size_t)zz * P];
        f.x += t.x; f.y += t.y; f.z += t.z; f.w += t.w;
    }
    t = ((const float4*)b2)[j];
    f.x += t.x; f.y += t.y; f.z += t.z; f.w += t.w;

    float4 v = ((const float4*)g_Vp)[off + j];
    #pragma unroll
    for (int zz = 1; zz < 4; zz++) {
        t = ((const float4*)g_Vp)[off + j + (size_t)zz * P];
        v.x += t.x; v.y += t.y; v.z += t.z; v.w += t.w;
    }

    float s = f.x * v.x + f.y * v.y + f.z * v.z + f.w * v.w;
    #pragma unroll
    for (int o = 16; o > 0; o >>= 1)
        s += __shfl_xor_sync(0xFFFFFFFFu, s, o);
    __shared__ float red[8];
    if ((threadIdx.x & 31) == 0) red[threadIdx.x >> 5] = s;
    __syncthreads();
    if (threadIdx.x < 8) {
        s = red[threadIdx.x];
        #pragma unroll
        for (int o = 4; o > 0; o >>= 1)
            s += __shfl_xor_sync(0xFFu, s, o);
        if (threadIdx.x == 0) out[b] = s * (1.0f / (float)NASPECT);
    }
}

// ---------------------------------------------------------------------------
#define SM_G1  (2 * (128 * (64 + 8) * 2 + 64 * (128 + 8) * 2))  // 71680
#define SM_G23 (2 * (64 * (64 + 8) * 2 + 64 * (128 + 8) * 2))   // 53248

extern "C" void kernel_launch(void* const* d_in, const int* in_sizes, int n_in,
                              void* d_out, int out_size)
{
    const float* image     = (const float*)d_in[0];
    const int*   brand     = (const int*)d_in[1];
    const float* W1        = (const float*)d_in[2];
    const float* b1        = (const float*)d_in[3];
    const float* W2        = (const float*)d_in[4];
    const float* b2        = (const float*)d_in[5];
    const float* brand_emb = (const float*)d_in[6];
    const float* aspects   = (const float*)d_in[7];
    float*       out       = (float*)d_out;

    static bool init = false;
    if (!init) {
        cudaFuncSetAttribute((const void*)gemm1_split,
                             cudaFuncAttributeMaxDynamicSharedMemorySize, SM_G1);
        cudaFuncSetAttribute((const void*)gemm23_split,
                             cudaFuncAttributeMaxDynamicSharedMemorySize, SM_G23);
        init = true;
    }

    // All operand conversions, one launch
    prep_all<<<4096, 256>>>(image, W1, W2, aspects, brand_emb, brand);

    // GEMM1 split-K4: Hp[z] = image_z @ W1_z   (512 CTAs)
    gemm1_split<<<dim3(FCIN / 128, BATCH / 128, 4), 256, SM_G1>>>();

    // Hf = fp16(lrelu(sum Hp + b1))
    h_finalize<<<2048, 256>>>(b1);

    // Fused GEMM2 split-K8 + GEMM3 split-K4  (768 CTAs, 64x128 tiles)
    gemm23_split<<<dim3(EMBED / 128, BATCH / 64, 12), 256, SM_G23>>>();

    // out = mean reduce of (ΣFp + b2)·(ΣVp)
    final_dot<<<BATCH, 256>>>(b2, out);
}